// round 9
// baseline (speedup 1.0000x reference)
#include <cuda_runtime.h>
#include <cuda_bf16.h>
#include <cstdint>

// ---------------------------------------------------------------------------
// HeteroGNN (3-layer hetero SAGE) on GB300 — Round 9.
//   R9: atomic scatter-mean replaced by CSR build (deg->scan->fill) +
//   warp-per-row gather aggregation fused with mean + bf16 hi/lo split.
//   Deletes zero_agg / scatter / agg_fin / inv kernels (~4 GB atomic traffic).
//   GEMMs stay on mma.sync bf16 (hi/lo, 3 passes) from R8.
// ---------------------------------------------------------------------------

#define DIM 256

static const int  NNODE[4]  = {100000, 50000, 200000, 150000};
static const long XOFF[4]   = {0, 100000, 150000, 350000};
static const int  ET_S[7]   = {2, 3, 1, 2, 3, 0, 0};
static const int  ET_D[7]   = {0, 0, 0, 1, 1, 2, 3};
static const long DEGOFF[7] = {0, 100000, 200000, 300000, 350000, 400000, 600000};
#define DEG_TOTAL 750000
#define NBLK_SCAN 733          // ceil(750000/1024)

__device__ float g_xA[128000000];
__device__ float g_xB[128000000];
__device__ int   g_deg[DEG_TOTAL];
__device__ int   g_off[DEG_TOTAL + 1];
__device__ int   g_cur[DEG_TOTAL];
__device__ int   g_bsum[1024];
__device__ int   g_pool[2400000];
__device__ float g_r1[8 * 256];
__device__ float g_two[2 * 256];

__device__ __nv_bfloat16 g_Whi[21 * 256 * 512];  // [pair][N=256][K=512]
__device__ __nv_bfloat16 g_Wlo[21 * 256 * 512];
__device__ __nv_bfloat16 g_aggh[51200000];
__device__ __nv_bfloat16 g_aggl[51200000];
__device__ __nv_bfloat16 g_xh[128000000];
__device__ __nv_bfloat16 g_xl[128000000];

// ---- FFMA2 helpers (head GEMM) ---------------------------------------------
#define PACK2(out, lo, hi) \
    asm("mov.b64 %0, {%1, %2};" : "=l"(out) : "r"(__float_as_uint(lo)), "r"(__float_as_uint(hi)))
#define FMA2(acc, a, b) \
    asm("fma.rn.f32x2 %0, %1, %2, %0;" : "+l"(acc) : "l"(a), "l"(b))
#define UNPACK2(lo, hi, in) do { \
    unsigned _ul, _uh; \
    asm("mov.b64 {%0, %1}, %2;" : "=r"(_ul), "=r"(_uh) : "l"(in)); \
    lo = __uint_as_float(_ul); hi = __uint_as_float(_uh); } while (0)

// ---- mma.sync helpers --------------------------------------------------------
__device__ __forceinline__ uint32_t smem_u32(const void* p) {
    uint32_t a;
    asm("{ .reg .u64 t; cvta.to.shared.u64 t, %1; cvt.u32.u64 %0, t; }" : "=r"(a) : "l"(p));
    return a;
}
__device__ __forceinline__ void cp16(uint32_t dst, const void* src, int sz) {
    asm volatile("cp.async.cg.shared.global [%0], [%1], 16, %2;"
                 :: "r"(dst), "l"(src), "r"(sz) : "memory");
}
#define CP_COMMIT() asm volatile("cp.async.commit_group;" ::: "memory")
#define CP_WAIT(N)  asm volatile("cp.async.wait_group %0;" :: "n"(N) : "memory")

#define LDSM4(r0, r1, r2, r3, addr) \
    asm volatile("ldmatrix.sync.aligned.m8n8.x4.shared.b16 {%0,%1,%2,%3}, [%4];" \
                 : "=r"(r0), "=r"(r1), "=r"(r2), "=r"(r3) : "r"(addr))

#define MMA16816(c, a, b) \
    asm volatile("mma.sync.aligned.m16n8k16.row.col.f32.bf16.bf16.f32 " \
                 "{%0,%1,%2,%3}, {%4,%5,%6,%7}, {%8,%9}, {%0,%1,%2,%3};" \
                 : "+f"((c)[0]), "+f"((c)[1]), "+f"((c)[2]), "+f"((c)[3]) \
                 : "r"((a)[0]), "r"((a)[1]), "r"((a)[2]), "r"((a)[3]), \
                   "r"((b)[0]), "r"((b)[1]))

__device__ __forceinline__ const float* resolve_x(const float* ext, int sel, long rowoff) {
    if (sel == 0) return g_xA + rowoff * DIM;
    if (sel == 1) return g_xB + rowoff * DIM;
    return ext;
}
__device__ __forceinline__ void bsplit(float v, __nv_bfloat16& h, __nv_bfloat16& l) {
    h = __float2bfloat16(v);
    l = __float2bfloat16(v - __bfloat162float(h));
}

// ---- CSR build ---------------------------------------------------------------
__global__ void zero_deg_kernel() {
    int i = blockIdx.x * blockDim.x + threadIdx.x;
    if (i < DEG_TOTAL) g_deg[i] = 0;
}
__global__ void deg_kernel(const int* __restrict__ dstIdx, int e, long degOff) {
    int i = blockIdx.x * blockDim.x + threadIdx.x;
    if (i < e) atomicAdd(&g_deg[degOff + dstIdx[i]], 1);
}
// block-level inclusive scan of deg; writes per-element exclusive, block totals
__global__ void scan1_kernel() {
    __shared__ int sh[1024];
    int tid = threadIdx.x;
    int gid = blockIdx.x * 1024 + tid;
    int v = (gid < DEG_TOTAL) ? g_deg[gid] : 0;
    sh[tid] = v;
    __syncthreads();
#pragma unroll
    for (int o = 1; o < 1024; o <<= 1) {
        int t = (tid >= o) ? sh[tid - o] : 0;
        __syncthreads();
        sh[tid] += t;
        __syncthreads();
    }
    if (gid < DEG_TOTAL) g_off[gid] = sh[tid] - v;   // exclusive within block
    if (tid == 1023) g_bsum[blockIdx.x] = sh[1023];
}
__global__ void scan2_kernel() {
    __shared__ int sh[1024];
    int tid = threadIdx.x;
    int v = (tid < NBLK_SCAN) ? g_bsum[tid] : 0;
    sh[tid] = v;
    __syncthreads();
#pragma unroll
    for (int o = 1; o < 1024; o <<= 1) {
        int t = (tid >= o) ? sh[tid - o] : 0;
        __syncthreads();
        sh[tid] += t;
        __syncthreads();
    }
    if (tid < NBLK_SCAN) g_bsum[tid] = sh[tid] - v;  // exclusive block bases
    if (tid == NBLK_SCAN - 1) g_off[DEG_TOTAL] = sh[tid];   // grand total
}
__global__ void scan3_kernel() {
    int gid = blockIdx.x * 1024 + threadIdx.x;
    if (gid < DEG_TOTAL) {
        int o = g_off[gid] + g_bsum[blockIdx.x];
        g_off[gid] = o;
        g_cur[gid] = o;
    }
}
__global__ void fill_kernel(const int* __restrict__ srcIdx,
                            const int* __restrict__ dstIdx, int e, long degOff) {
    int i = blockIdx.x * blockDim.x + threadIdx.x;
    if (i >= e) return;
    int pos = atomicAdd(&g_cur[degOff + dstIdx[i]], 1);
    g_pool[pos] = srcIdx[i];
}

// ---- gather aggregation: warp per dst row; mean + bf16 split -----------------
__global__ void agg_gather_kernel(const float* __restrict__ ext, int sel, long xoff,
                                  long degoff, int n, int relu) {
    int g = blockIdx.x * blockDim.x + threadIdx.x;
    long r = g >> 5;
    if (r >= n) return;
    int lane = g & 31;
    const float* X = resolve_x(ext, sel, xoff);
    int start = g_off[degoff + r];
    int end   = g_off[degoff + r + 1];
    float4 a0 = make_float4(0.f, 0.f, 0.f, 0.f);
    float4 a1 = make_float4(0.f, 0.f, 0.f, 0.f);
    for (int j = start; j < end; j++) {
        long s = g_pool[j];
        const float4* row = (const float4*)(X + s * DIM);
        float4 v0 = __ldg(&row[lane]);
        float4 v1 = __ldg(&row[lane + 32]);
        if (relu) {
            v0.x = fmaxf(v0.x, 0.f); v0.y = fmaxf(v0.y, 0.f);
            v0.z = fmaxf(v0.z, 0.f); v0.w = fmaxf(v0.w, 0.f);
            v1.x = fmaxf(v1.x, 0.f); v1.y = fmaxf(v1.y, 0.f);
            v1.z = fmaxf(v1.z, 0.f); v1.w = fmaxf(v1.w, 0.f);
        }
        a0.x += v0.x; a0.y += v0.y; a0.z += v0.z; a0.w += v0.w;
        a1.x += v1.x; a1.y += v1.y; a1.z += v1.z; a1.w += v1.w;
    }
    float inv = 1.0f / fmaxf((float)(end - start), 1.0f);
    float v[8] = {a0.x * inv, a0.y * inv, a0.z * inv, a0.w * inv,
                  a1.x * inv, a1.y * inv, a1.z * inv, a1.w * inv};
    __align__(8) __nv_bfloat16 h0[4], l0[4], h1[4], l1[4];
#pragma unroll
    for (int q = 0; q < 4; q++) { bsplit(v[q], h0[q], l0[q]); bsplit(v[4 + q], h1[q], l1[q]); }
    long base = r * DIM;
    *(uint2*)(g_aggh + base + lane * 4)       = *(const uint2*)h0;
    *(uint2*)(g_aggh + base + 128 + lane * 4) = *(const uint2*)h1;
    *(uint2*)(g_aggl + base + lane * 4)       = *(const uint2*)l0;
    *(uint2*)(g_aggl + base + 128 + lane * 4) = *(const uint2*)l1;
}

// ---- misc small kernels -------------------------------------------------------
__global__ void rank1_kernel(const float* __restrict__ v, const float* __restrict__ W,
                             float* __restrict__ out) {
    int j = threadIdx.x;
    float acc = 0.f;
#pragma unroll 8
    for (int k = 0; k < 256; k++) acc += __ldg(&v[k]) * __ldg(&W[k * 256 + j]);
    out[j] = acc;
}
__global__ void t2_combine_kernel(const float* __restrict__ vl, const float* __restrict__ vr,
                                  const float* __restrict__ b) {
    __shared__ float red[2][8];
    int j = threadIdx.x;
    float a0 = vr[j] + b[j];
    float a1 = a0 + vl[j];
    float s0 = a0 * a0, s1 = a1 * a1;
#pragma unroll
    for (int o = 16; o > 0; o >>= 1) {
        s0 += __shfl_xor_sync(0xffffffffu, s0, o);
        s1 += __shfl_xor_sync(0xffffffffu, s1, o);
    }
    if ((j & 31) == 0) { red[0][j >> 5] = s0; red[1][j >> 5] = s1; }
    __syncthreads();
    float t0 = 0.f, t1 = 0.f;
#pragma unroll
    for (int w = 0; w < 8; w++) { t0 += red[0][w]; t1 += red[1][w]; }
    g_two[j]       = a0 * (1.0f / fmaxf(sqrtf(t0), 1e-12f));
    g_two[256 + j] = a1 * (1.0f / fmaxf(sqrtf(t1), 1e-12f));
}
__global__ void t2_apply_kernel(float* __restrict__ Out, long degoff, int n) {
    long i = (long)blockIdx.x * blockDim.x + threadIdx.x;
    long r = i >> 6;
    int c = (int)(i & 63);
    if (r >= n) return;
    int gate = g_deg[degoff + r] > 0 ? 1 : 0;
    float4 w = ((const float4*)(g_two + gate * 256))[c];
    float4 u = ((float4*)(Out + r * DIM))[c];
    u.x += w.x; u.y += w.y; u.z += w.z; u.w += w.w;
    ((float4*)(Out + r * DIM))[c] = u;
}

// ---- conversion kernels --------------------------------------------------------
__global__ void conv_w_kernel(const float* __restrict__ Wl, const float* __restrict__ Wr) {
    long i = (long)blockIdx.x * blockDim.x + threadIdx.x;
    if (i >= 21L * 256 * 64) return;
    int p    = (int)(i / (256 * 64));
    int rem  = (int)(i % (256 * 64));
    int nrow = rem / 64;
    int k8   = (rem % 64) * 8;
    const float* base = ((k8 < 256) ? Wl : Wr) + (long)p * 65536;
    int kk = k8 & 255;
    __align__(16) __nv_bfloat16 h[8], l[8];
#pragma unroll
    for (int j = 0; j < 8; j++) {
        float v = __ldg(&base[(long)(kk + j) * 256 + nrow]);
        bsplit(v, h[j], l[j]);
    }
    long o = ((long)p * 256 + nrow) * 512 + k8;
    *(uint4*)(g_Whi + o) = *(const uint4*)h;
    *(uint4*)(g_Wlo + o) = *(const uint4*)l;
}

__global__ void conv_x_kernel(const float* __restrict__ src, long dstRow, long n8, int relu) {
    long i = (long)blockIdx.x * blockDim.x + threadIdx.x;
    if (i >= n8) return;
    float4 a = ((const float4*)src)[i * 2];
    float4 b = ((const float4*)src)[i * 2 + 1];
    if (relu) {
        a.x = fmaxf(a.x, 0.f); a.y = fmaxf(a.y, 0.f); a.z = fmaxf(a.z, 0.f); a.w = fmaxf(a.w, 0.f);
        b.x = fmaxf(b.x, 0.f); b.y = fmaxf(b.y, 0.f); b.z = fmaxf(b.z, 0.f); b.w = fmaxf(b.w, 0.f);
    }
    float v[8] = {a.x, a.y, a.z, a.w, b.x, b.y, b.z, b.w};
    __align__(16) __nv_bfloat16 h[8], l[8];
#pragma unroll
    for (int j = 0; j < 8; j++) bsplit(v[j], h[j], l[j]);
    *(uint4*)(g_xh + dstRow * 256 + i * 8) = *(const uint4*)h;
    *(uint4*)(g_xl + dstRow * 256 + i * 8) = *(const uint4*)l;
}

// ---- mma.sync fused SAGE GEMM (unchanged from R8) ------------------------------
#define A_STRIDE 144
#define A_BLK    (64 * 144)
#define B_OFF    36864
#define B_BLK    (256 * 144)
#define CADD_OFF 184320
#define CVG_OFF  185344
#define RED_OFF  186368
#define SMEM_SZ  187392

__global__ __launch_bounds__(256, 1) void mma_sage(
    long xoff,
    const __nv_bfloat16* __restrict__ Wh, const __nv_bfloat16* __restrict__ Wlo_,
    const float* __restrict__ bias, const float* __restrict__ cvA,
    const float* __restrict__ cvG,
    float* __restrict__ Out, long degoff, int n, int accum, int nagg, int nx) {
    extern __shared__ char smem[];
    const int tid = threadIdx.x;
    const int lane = tid & 31, wid = tid >> 5;
    const int wm = wid >> 2, wn = wid & 3;
    const uint32_t sbase = smem_u32(smem);
    float* cadd   = (float*)(smem + CADD_OFF);
    float* cvgS   = (float*)(smem + CVG_OFF);
    float* rowred = (float*)(smem + RED_OFF);

    cadd[tid] = bias[tid] + (cvA ? cvA[tid] : 0.f);
    cvgS[tid] = cvG ? cvG[tid] : 0.f;

    const long row0 = (long)blockIdx.x * 64;
    const int nch = nagg + nx;

    float C[2][8][4];
#pragma unroll
    for (int mt = 0; mt < 2; mt++)
#pragma unroll
        for (int nt = 0; nt < 8; nt++)
#pragma unroll
            for (int q = 0; q < 4; q++) C[mt][nt][q] = 0.f;

    const int aslot = tid >> 1, avar = aslot >> 6, arow = aslot & 63;
    const int akh = (tid & 1) * 32;
    const long agrow = row0 + arow;
    const int asz = (agrow < n) ? 16 : 0;
    const long agc = (agrow < n) ? agrow : 0;

    auto issue = [&](int s, int c) {
        int kcol, wcol;
        const __nv_bfloat16 *Ah, *Al;
        if (c < nagg) { Ah = g_aggh; Al = g_aggl; kcol = c * 64; wcol = c * 64; }
        else {
            Ah = g_xh + xoff * 256; Al = g_xl + xoff * 256;
            kcol = (c - nagg) * 64; wcol = 256 + (c - nagg) * 64;
        }
        const __nv_bfloat16* asrc = (avar ? Al : Ah) + agc * 256 + kcol + akh;
        uint32_t adst = sbase + (uint32_t)(s * 2 + avar) * A_BLK + arow * A_STRIDE + akh * 2;
#pragma unroll
        for (int j = 0; j < 4; j++) cp16(adst + j * 16, asrc + j * 8, asz);
#pragma unroll
        for (int v = 0; v < 2; v++) {
            const __nv_bfloat16* b = (v ? Wlo_ : Wh) + (long)tid * 512 + wcol;
            uint32_t bdst = sbase + B_OFF + (uint32_t)(s * 2 + v) * B_BLK + tid * A_STRIDE;
#pragma unroll
            for (int j = 0; j < 8; j++) cp16(bdst + j * 16, b + j * 8, 16);
        }
        CP_COMMIT();
    };

    issue(0, 0);
    if (nch > 1) issue(1, 1);

    const int a_r  = wm * 32 + (lane & 15);
    const int a_k8 = ((lane >> 4) & 1) * 8;
    const int b_n  = ((lane >> 4) & 1) * 8 + (lane & 7);
    const int b_k8 = ((lane >> 3) & 1) * 8;

    for (int c = 0; c < nch; c++) {
        if (c + 1 < nch) { CP_WAIT(1); } else { CP_WAIT(0); }
        __syncthreads();
        const int s = c & 1;
        const uint32_t aBase = sbase + (uint32_t)(s * 2) * A_BLK;
        const uint32_t bBase = sbase + B_OFF + (uint32_t)(s * 2) * B_BLK;

#pragma unroll
        for (int k16 = 0; k16 < 4; k16++) {
            const int kb = k16 * 16;
            uint32_t ah[2][4], al[2][4], bh[8][2], bl[8][2];
#pragma unroll
            for (int mt = 0; mt < 2; mt++) {
                uint32_t ad = aBase + (a_r + mt * 16) * A_STRIDE + (kb + a_k8) * 2;
                LDSM4(ah[mt][0], ah[mt][1], ah[mt][2], ah[mt][3], ad);
                LDSM4(al[mt][0], al[mt][1], al[mt][2], al[mt][3], ad + A_BLK);
            }
#pragma unroll
            for (int np = 0; np < 4; np++) {
                uint32_t bd = bBase + (wn * 64 + np * 16 + b_n) * A_STRIDE + (kb + b_k8) * 2;
                LDSM4(bh[np*2][0], bh[np*2][1], bh[np*2+1][0], bh[np*2+1][1], bd);
                LDSM4(bl[np*2][0], bl[np*2][1], bl[np*2+1][0], bl[np*2+1][1], bd + B_BLK);
            }
#pragma unroll
            for (int mt = 0; mt < 2; mt++)
#pragma unroll
                for (int nt = 0; nt < 8; nt++) {
                    MMA16816(C[mt][nt], ah[mt], bh[nt]);
                    MMA16816(C[mt][nt], al[mt], bh[nt]);
                    MMA16816(C[mt][nt], ah[mt], bl[nt]);
                }
        }
        __syncthreads();
        if (c + 2 < nch) issue(s, c + 2);
    }

    float gate_lo[2], gate_hi[2];
#pragma unroll
    for (int mt = 0; mt < 2; mt++) {
        int rl = wm * 32 + mt * 16 + (lane >> 2);
        long grl = row0 + rl, grh = grl + 8;
        gate_lo[mt] = (cvG && grl < n) ? ((g_deg[degoff + grl] > 0) ? 1.f : 0.f) : 0.f;
        gate_hi[mt] = (cvG && grh < n) ? ((g_deg[degoff + grh] > 0) ? 1.f : 0.f) : 0.f;
    }
    float s_lo[2] = {0.f, 0.f}, s_hi[2] = {0.f, 0.f};
#pragma unroll
    for (int mt = 0; mt < 2; mt++)
#pragma unroll
        for (int nt = 0; nt < 8; nt++) {
            int col = wn * 64 + nt * 8 + (lane & 3) * 2;
            float c0 = cadd[col], c1 = cadd[col + 1];
            float g0 = cvgS[col], g1 = cvgS[col + 1];
            float v0 = C[mt][nt][0] + c0 + gate_lo[mt] * g0;
            float v1 = C[mt][nt][1] + c1 + gate_lo[mt] * g1;
            float v2 = C[mt][nt][2] + c0 + gate_hi[mt] * g0;
            float v3 = C[mt][nt][3] + c1 + gate_hi[mt] * g1;
            C[mt][nt][0] = v0; C[mt][nt][1] = v1; C[mt][nt][2] = v2; C[mt][nt][3] = v3;
            s_lo[mt] += v0 * v0 + v1 * v1;
            s_hi[mt] += v2 * v2 + v3 * v3;
        }
#pragma unroll
    for (int mt = 0; mt < 2; mt++) {
        s_lo[mt] += __shfl_xor_sync(0xffffffffu, s_lo[mt], 1);
        s_lo[mt] += __shfl_xor_sync(0xffffffffu, s_lo[mt], 2);
        s_hi[mt] += __shfl_xor_sync(0xffffffffu, s_hi[mt], 1);
        s_hi[mt] += __shfl_xor_sync(0xffffffffu, s_hi[mt], 2);
    }
    if ((lane & 3) == 0) {
#pragma unroll
        for (int mt = 0; mt < 2; mt++) {
            int rl = wm * 32 + mt * 16 + (lane >> 2);
            rowred[wn * 64 + rl]     = s_lo[mt];
            rowred[wn * 64 + rl + 8] = s_hi[mt];
        }
    }
    __syncthreads();
#pragma unroll
    for (int mt = 0; mt < 2; mt++) {
        int rl = wm * 32 + mt * 16 + (lane >> 2);
        int rh = rl + 8;
        float ssl = rowred[rl] + rowred[64 + rl] + rowred[128 + rl] + rowred[192 + rl];
        float ssh = rowred[rh] + rowred[64 + rh] + rowred[128 + rh] + rowred[192 + rh];
        float scl = 1.0f / fmaxf(sqrtf(ssl), 1e-12f);
        float sch = 1.0f / fmaxf(sqrtf(ssh), 1e-12f);
        long grl = row0 + rl, grh = row0 + rh;
#pragma unroll
        for (int nt = 0; nt < 8; nt++) {
            int col = wn * 64 + nt * 8 + (lane & 3) * 2;
            if (grl < n) {
                float2 o = make_float2(C[mt][nt][0] * scl, C[mt][nt][1] * scl);
                float* op = Out + grl * 256 + col;
                if (accum) { float2 u = *(const float2*)op; o.x += u.x; o.y += u.y; }
                *(float2*)op = o;
            }
            if (grh < n) {
                float2 o = make_float2(C[mt][nt][2] * sch, C[mt][nt][3] * sch);
                float* op = Out + grh * 256 + col;
                if (accum) { float2 u = *(const float2*)op; o.x += u.x; o.y += u.y; }
                *(float2*)op = o;
            }
        }
    }
}

// ---- final head: relu(x_reaction) @ W_out[256x128] + b_out ---------------------
__global__ __launch_bounds__(256, 2) void final_gemm(
    int asel, long aoff, const float* __restrict__ W,
    const float* __restrict__ bias, float* __restrict__ C, int n) {
    __shared__ float As[16][64];
    __shared__ float Bs[16][128];
    const int tid = threadIdx.x;
    const long row0 = (long)blockIdx.x * 64;
    const int m = tid & 63, kq = tid >> 6;
    const int jb = tid & 31, kb2 = tid >> 5;
    const int tcol = tid & 31, tr = tid >> 5;

    const float* A = resolve_x(nullptr, asel, aoff);

    unsigned long long acc[8][2];
#pragma unroll
    for (int i = 0; i < 8; i++) { acc[i][0] = 0ULL; acc[i][1] = 0ULL; }

    const long arow = row0 + m;
    const bool aval = arow < n;

#pragma unroll 1
    for (int k0 = 0; k0 < 256; k0 += 16) {
        float4 av = make_float4(0.f, 0.f, 0.f, 0.f);
        if (aval) av = *(const float4*)&A[arow * DIM + k0 + kq * 4];
        av.x = fmaxf(av.x, 0.f); av.y = fmaxf(av.y, 0.f);
        av.z = fmaxf(av.z, 0.f); av.w = fmaxf(av.w, 0.f);
        float4 bv0 = *(const float4*)&W[(long)(k0 + kb2) * 128 + jb * 4];
        float4 bv1 = *(const float4*)&W[(long)(k0 + kb2 + 8) * 128 + jb * 4];
        __syncthreads();
        As[kq * 4 + 0][m] = av.x;
        As[kq * 4 + 1][m] = av.y;
        As[kq * 4 + 2][m] = av.z;
        As[kq * 4 + 3][m] = av.w;
        *(float4*)&Bs[kb2][jb * 4] = bv0;
        *(float4*)&Bs[kb2 + 8][jb * 4] = bv1;
        __syncthreads();
#pragma unroll
        for (int k = 0; k < 16; k++) {
            ulonglong2 b01 = *(const ulonglong2*)&Bs[k][tcol * 4];
            float4 a0 = *(const float4*)&As[k][tr * 8];
            float4 a1 = *(const float4*)&As[k][tr * 8 + 4];
            float aa[8] = {a0.x, a0.y, a0.z, a0.w, a1.x, a1.y, a1.z, a1.w};
#pragma unroll
            for (int i = 0; i < 8; i++) {
                unsigned long long a2v;
                PACK2(a2v, aa[i], aa[i]);
                FMA2(acc[i][0], a2v, b01.x);
                FMA2(acc[i][1], a2v, b01.y);
            }
        }
    }

    float4 bb = *(const float4*)&bias[tcol * 4];
    float bsv[4] = {bb.x, bb.y, bb.z, bb.w};
#pragma unroll
    for (int i = 0; i < 8; i++) {
        float v[4];
        UNPACK2(v[0], v[1], acc[i][0]);
        UNPACK2(v[2], v[3], acc[i][1]);
        long r = row0 + (long)tr * 8 + i;
        if (r < n) {
            float4 o0 = make_float4(v[0] + bsv[0], v[1] + bsv[1],
                                    v[2] + bsv[2], v[3] + bsv[3]);
            *(float4*)&C[r * 128 + tcol * 4] = o0;
        }
    }
}

// ---------------------------------------------------------------------------
extern "C" void kernel_launch(void* const* d_in, const int* in_sizes, int n_in,
                              void* d_out, int out_size) {
    const float* remb = (const float*)d_in[4];
    const float* cemb = (const float*)d_in[5];
    const float* ptab = (const float*)d_in[6];
    const float* mtab = (const float*)d_in[7];
    const float* Wl   = (const float*)d_in[8];
    const float* Wr   = (const float*)d_in[9];
    const float* bvec = (const float*)d_in[10];
    const float* Wout = (const float*)d_in[11];
    const float* bout = (const float*)d_in[12];
    const int* edge[7];
    int ecnt[7];
    for (int t = 0; t < 7; t++) {
        edge[t] = (const int*)d_in[13 + t];
        ecnt[t] = in_sizes[13 + t] / 2;
    }

    cudaFuncSetAttribute(mma_sage, cudaFuncAttributeMaxDynamicSharedMemorySize, SMEM_SZ);

    float *r1, *xA, *xB;
    __nv_bfloat16 *whi, *wlo;
    cudaGetSymbolAddress((void**)&r1, g_r1);
    cudaGetSymbolAddress((void**)&xA, g_xA);
    cudaGetSymbolAddress((void**)&xB, g_xB);
    cudaGetSymbolAddress((void**)&whi, g_Whi);
    cudaGetSymbolAddress((void**)&wlo, g_Wlo);

    // CSR build: deg -> scan -> fill (+ g_deg kept for epilogue gates)
    zero_deg_kernel<<<(DEG_TOTAL + 255) / 256, 256>>>();
    for (int t = 0; t < 7; t++)
        deg_kernel<<<(ecnt[t] + 255) / 256, 256>>>(edge[t] + ecnt[t], ecnt[t], DEGOFF[t]);
    scan1_kernel<<<NBLK_SCAN, 1024>>>();
    scan2_kernel<<<1, 1024>>>();
    scan3_kernel<<<NBLK_SCAN, 1024>>>();
    for (int t = 0; t < 7; t++)
        fill_kernel<<<(ecnt[t] + 255) / 256, 256>>>(edge[t], edge[t] + ecnt[t], ecnt[t], DEGOFF[t]);

    // weight repack + layer-0 table conversion
    conv_w_kernel<<<(int)((21L * 256 * 64 + 255) / 256), 256>>>(Wl, Wr);
    conv_x_kernel<<<(int)((200000L * 32 + 255) / 256), 256>>>(ptab, XOFF[2], 200000L * 32, 0);
    conv_x_kernel<<<(int)((150000L * 32 + 255) / 256), 256>>>(mtab, XOFF[3], 150000L * 32, 0);

    // layer-0 rank-1 vectors
    rank1_kernel<<<1, 256>>>(remb, Wr + 0 * 65536L, r1 + 0 * 256);
    rank1_kernel<<<1, 256>>>(remb, Wr + 1 * 65536L, r1 + 1 * 256);
    rank1_kernel<<<1, 256>>>(cemb, Wl + 2 * 65536L, r1 + 2 * 256);
    rank1_kernel<<<1, 256>>>(remb, Wr + 2 * 65536L, r1 + 3 * 256);
    rank1_kernel<<<1, 256>>>(cemb, Wr + 3 * 65536L, r1 + 4 * 256);
    rank1_kernel<<<1, 256>>>(cemb, Wr + 4 * 65536L, r1 + 5 * 256);
    rank1_kernel<<<1, 256>>>(remb, Wl + 5 * 65536L, r1 + 6 * 256);
    rank1_kernel<<<1, 256>>>(remb, Wl + 6 * 65536L, r1 + 7 * 256);
    t2_combine_kernel<<<1, 256>>>(r1 + 2 * 256, r1 + 3 * 256, bvec + 2 * 256);

    const float* src_ext[2] = {ptab, mtab};

    // ---------------- layer 0 ----------------
    for (int t = 0; t < 2; t++) {     // dst reaction: agg GEMM + const
        int nd = NNODE[0];
        agg_gather_kernel<<<(int)(((long)nd * 32 + 255) / 256), 256>>>(
            src_ext[t], 2, 0, DEGOFF[t], nd, 0);
        mma_sage<<<(nd + 63) / 64, 256, SMEM_SZ>>>(
            0, whi + (long)t * 131072, wlo + (long)t * 131072,
            bvec + (long)t * 256, r1 + t * 256, nullptr,
            xB + XOFF[0] * DIM, DEGOFF[t], nd, t == 0 ? 0 : 1, 4, 0);
    }
    t2_apply_kernel<<<(NNODE[0] * 64 + 255) / 256, 256>>>(xB + XOFF[0] * DIM, DEGOFF[2], NNODE[0]);
    for (int t = 3; t < 5; t++) {     // dst complex: agg GEMM + const
        int nd = NNODE[1];
        agg_gather_kernel<<<(int)(((long)nd * 32 + 255) / 256), 256>>>(
            src_ext[t - 3], 2, 0, DEGOFF[t], nd, 0);
        mma_sage<<<(nd + 63) / 64, 256, SMEM_SZ>>>(
            0, whi + (long)t * 131072, wlo + (long)t * 131072,
            bvec + (long)t * 256, r1 + (t + 1) * 256, nullptr,
            xB + XOFF[1] * DIM, DEGOFF[t], nd, t == 3 ? 0 : 1, 4, 0);
    }
    // t5: gate*vl + ptab@Wr (x-phase only), dst protein
    mma_sage<<<(NNODE[2] + 63) / 64, 256, SMEM_SZ>>>(
        XOFF[2], whi + 5L * 131072, wlo + 5L * 131072,
        bvec + 5L * 256, nullptr, r1 + 6 * 256,
        xB + XOFF[2] * DIM, DEGOFF[5], NNODE[2], 0, 0, 4);
    // t6: gate*vl + mtab@Wr, dst molecule
    mma_sage<<<(NNODE[3] + 63) / 64, 256, SMEM_SZ>>>(
        XOFF[3], whi + 6L * 131072, wlo + 6L * 131072,
        bvec + 6L * 256, nullptr, r1 + 7 * 256,
        xB + XOFF[3] * DIM, DEGOFF[6], NNODE[3], 0, 0, 4);

    // ---------------- layer 1 (reads xB -> writes xA) ----------------
    conv_x_kernel<<<(int)((500000L * 32 + 255) / 256), 256>>>(xB, 0, 500000L * 32, 1);
    {
        bool first[4] = {true, true, true, true};
        for (int t = 0; t < 7; t++) {
            int s = ET_S[t], d = ET_D[t];
            int nd = NNODE[d];
            agg_gather_kernel<<<(int)(((long)nd * 32 + 255) / 256), 256>>>(
                nullptr, 1, XOFF[s], DEGOFF[t], nd, 1);
            mma_sage<<<(nd + 63) / 64, 256, SMEM_SZ>>>(
                XOFF[d], whi + (long)(7 + t) * 131072, wlo + (long)(7 + t) * 131072,
                bvec + (long)(7 + t) * 256, nullptr, nullptr,
                xA + XOFF[d] * DIM, DEGOFF[t], nd, first[d] ? 0 : 1, 4, 4);
            first[d] = false;
        }
    }

    // ---------------- layer 2 (reads xA -> writes xB, dst reaction only) -------
    conv_x_kernel<<<(int)((100000L * 32 + 255) / 256), 256>>>(xA, 0, 100000L * 32, 1);
    for (int t = 0; t < 3; t++) {
        int s = ET_S[t];
        int nd = NNODE[0];
        agg_gather_kernel<<<(int)(((long)nd * 32 + 255) / 256), 256>>>(
            nullptr, 0, XOFF[s], DEGOFF[t], nd, 1);
        mma_sage<<<(nd + 63) / 64, 256, SMEM_SZ>>>(
            XOFF[0], whi + (long)(14 + t) * 131072, wlo + (long)(14 + t) * 131072,
            bvec + (long)(14 + t) * 256, nullptr, nullptr,
            xB + XOFF[0] * DIM, DEGOFF[t], nd, t == 0 ? 0 : 1, 4, 4);
    }

    // head: relu(x_reaction, in xB) @ W_out + b_out
    final_gemm<<<(NNODE[0] + 63) / 64, 256>>>(1, XOFF[0], Wout, bout, (float*)d_out, NNODE[0]);
}

// round 10
// speedup vs baseline: 1.3845x; 1.3845x over previous
#include <cuda_runtime.h>
#include <cuda_bf16.h>
#include <cstdint>

// ---------------------------------------------------------------------------
// HeteroGNN (3-layer hetero SAGE) on GB300 — Round 10.
//   R10 = R8 (atomic scatter + mma.sync bf16 hi/lo GEMM) with the bf16
//   conversion kernels (agg_fin, conv_x, inv) fused into the mma_sage
//   A-tile producer: LDG fp32 -> mean/relu -> bsplit -> STS. ~4.6 GB less
//   traffic, 28 fewer launches. CSR path from R9 reverted (it regressed).
// ---------------------------------------------------------------------------

#define DIM 256

static const int  NNODE[4]  = {100000, 50000, 200000, 150000};
static const long XOFF[4]   = {0, 100000, 150000, 350000};
static const int  ET_S[7]   = {2, 3, 1, 2, 3, 0, 0};
static const int  ET_D[7]   = {0, 0, 0, 1, 1, 2, 3};
static const long DEGOFF[7] = {0, 100000, 200000, 300000, 350000, 400000, 600000};
#define DEG_TOTAL 750000

__device__ float g_xA[128000000];
__device__ float g_xB[128000000];
__device__ float g_agg[51200000];
__device__ int   g_deg[DEG_TOTAL];
__device__ float g_r1[8 * 256];
__device__ float g_two[2 * 256];
__device__ __nv_bfloat16 g_Whi[21 * 256 * 512];  // [pair][N=256][K=512]
__device__ __nv_bfloat16 g_Wlo[21 * 256 * 512];

// ---- FFMA2 helpers (head GEMM) ---------------------------------------------
#define PACK2(out, lo, hi) \
    asm("mov.b64 %0, {%1, %2};" : "=l"(out) : "r"(__float_as_uint(lo)), "r"(__float_as_uint(hi)))
#define FMA2(acc, a, b) \
    asm("fma.rn.f32x2 %0, %1, %2, %0;" : "+l"(acc) : "l"(a), "l"(b))
#define UNPACK2(lo, hi, in) do { \
    unsigned _ul, _uh; \
    asm("mov.b64 {%0, %1}, %2;" : "=r"(_ul), "=r"(_uh) : "l"(in)); \
    lo = __uint_as_float(_ul); hi = __uint_as_float(_uh); } while (0)

__device__ __forceinline__ void red4(float* p, float4 v) {
    asm volatile("red.global.add.v4.f32 [%0], {%1,%2,%3,%4};"
                 :: "l"(p), "f"(v.x), "f"(v.y), "f"(v.z), "f"(v.w) : "memory");
}

// ---- mma.sync helpers --------------------------------------------------------
__device__ __forceinline__ uint32_t smem_u32(const void* p) {
    uint32_t a;
    asm("{ .reg .u64 t; cvta.to.shared.u64 t, %1; cvt.u32.u64 %0, t; }" : "=r"(a) : "l"(p));
    return a;
}
__device__ __forceinline__ void cp16(uint32_t dst, const void* src, int sz) {
    asm volatile("cp.async.cg.shared.global [%0], [%1], 16, %2;"
                 :: "r"(dst), "l"(src), "r"(sz) : "memory");
}
#define CP_COMMIT() asm volatile("cp.async.commit_group;" ::: "memory")
#define CP_WAIT(N)  asm volatile("cp.async.wait_group %0;" :: "n"(N) : "memory")

#define LDSM4(r0, r1, r2, r3, addr) \
    asm volatile("ldmatrix.sync.aligned.m8n8.x4.shared.b16 {%0,%1,%2,%3}, [%4];" \
                 : "=r"(r0), "=r"(r1), "=r"(r2), "=r"(r3) : "r"(addr))

#define MMA16816(c, a, b) \
    asm volatile("mma.sync.aligned.m16n8k16.row.col.f32.bf16.bf16.f32 " \
                 "{%0,%1,%2,%3}, {%4,%5,%6,%7}, {%8,%9}, {%0,%1,%2,%3};" \
                 : "+f"((c)[0]), "+f"((c)[1]), "+f"((c)[2]), "+f"((c)[3]) \
                 : "r"((a)[0]), "r"((a)[1]), "r"((a)[2]), "r"((a)[3]), \
                   "r"((b)[0]), "r"((b)[1]))

#define STS128(ad, a, b, c, d) \
    asm volatile("st.shared.v4.b32 [%0], {%1, %2, %3, %4};" \
                 :: "r"(ad), "r"(a), "r"(b), "r"(c), "r"(d) : "memory")

__device__ __forceinline__ const float* resolve_x(const float* ext, int sel, long rowoff) {
    if (sel == 0) return g_xA + rowoff * DIM;
    if (sel == 1) return g_xB + rowoff * DIM;
    return ext;
}
__device__ __forceinline__ void bsplit(float v, __nv_bfloat16& h, __nv_bfloat16& l) {
    h = __float2bfloat16(v);
    l = __float2bfloat16(v - __bfloat162float(h));
}

// ---- degree / aggregation kernels ---------------------------------------------
__global__ void zero_deg_kernel() {
    int i = blockIdx.x * blockDim.x + threadIdx.x;
    if (i < DEG_TOTAL) g_deg[i] = 0;
}
__global__ void deg_kernel(const int* __restrict__ dstIdx, int e, long degOff) {
    int i = blockIdx.x * blockDim.x + threadIdx.x;
    if (i < e) atomicAdd(&g_deg[degOff + dstIdx[i]], 1);
}
__global__ void zero_agg_kernel(long n4) {
    long i = (long)blockIdx.x * blockDim.x + threadIdx.x;
    if (i < n4) ((float4*)g_agg)[i] = make_float4(0.f, 0.f, 0.f, 0.f);
}
__global__ void scatter_kernel(const float* __restrict__ ext, int sel, long rowoff,
                               const int* __restrict__ srcIdx,
                               const int* __restrict__ dstIdx, int e, int relu) {
    int g = blockIdx.x * blockDim.x + threadIdx.x;
    int w = g >> 5;
    if (w >= e) return;
    int lane = g & 31;
    const float* X = resolve_x(ext, sel, rowoff);
    long s = srcIdx[w];
    long d = dstIdx[w];
    const float4* a = (const float4*)(X + s * DIM);
    float4 v0 = __ldg(&a[lane]);
    float4 v1 = __ldg(&a[lane + 32]);
    if (relu) {
        v0.x = fmaxf(v0.x, 0.f); v0.y = fmaxf(v0.y, 0.f);
        v0.z = fmaxf(v0.z, 0.f); v0.w = fmaxf(v0.w, 0.f);
        v1.x = fmaxf(v1.x, 0.f); v1.y = fmaxf(v1.y, 0.f);
        v1.z = fmaxf(v1.z, 0.f); v1.w = fmaxf(v1.w, 0.f);
    }
    float* o = g_agg + d * DIM;
    red4(o + lane * 4, v0);
    red4(o + 128 + lane * 4, v1);
}

// ---- misc small kernels ---------------------------------------------------------
__global__ void rank1_kernel(const float* __restrict__ v, const float* __restrict__ W,
                             float* __restrict__ out) {
    int j = threadIdx.x;
    float acc = 0.f;
#pragma unroll 8
    for (int k = 0; k < 256; k++) acc += __ldg(&v[k]) * __ldg(&W[k * 256 + j]);
    out[j] = acc;
}
__global__ void t2_combine_kernel(const float* __restrict__ vl, const float* __restrict__ vr,
                                  const float* __restrict__ b) {
    __shared__ float red[2][8];
    int j = threadIdx.x;
    float a0 = vr[j] + b[j];
    float a1 = a0 + vl[j];
    float s0 = a0 * a0, s1 = a1 * a1;
#pragma unroll
    for (int o = 16; o > 0; o >>= 1) {
        s0 += __shfl_xor_sync(0xffffffffu, s0, o);
        s1 += __shfl_xor_sync(0xffffffffu, s1, o);
    }
    if ((j & 31) == 0) { red[0][j >> 5] = s0; red[1][j >> 5] = s1; }
    __syncthreads();
    float t0 = 0.f, t1 = 0.f;
#pragma unroll
    for (int w = 0; w < 8; w++) { t0 += red[0][w]; t1 += red[1][w]; }
    g_two[j]       = a0 * (1.0f / fmaxf(sqrtf(t0), 1e-12f));
    g_two[256 + j] = a1 * (1.0f / fmaxf(sqrtf(t1), 1e-12f));
}
__global__ void t2_apply_kernel(float* __restrict__ Out, long degoff, int n) {
    long i = (long)blockIdx.x * blockDim.x + threadIdx.x;
    long r = i >> 6;
    int c = (int)(i & 63);
    if (r >= n) return;
    int gate = g_deg[degoff + r] > 0 ? 1 : 0;
    float4 w = ((const float4*)(g_two + gate * 256))[c];
    float4 u = ((float4*)(Out + r * DIM))[c];
    u.x += w.x; u.y += w.y; u.z += w.z; u.w += w.w;
    ((float4*)(Out + r * DIM))[c] = u;
}

// ---- weight repack: [pair][N=256][K=512] bf16 hi/lo ------------------------------
__global__ void conv_w_kernel(const float* __restrict__ Wl, const float* __restrict__ Wr) {
    long i = (long)blockIdx.x * blockDim.x + threadIdx.x;
    if (i >= 21L * 256 * 64) return;
    int p    = (int)(i / (256 * 64));
    int rem  = (int)(i % (256 * 64));
    int nrow = rem / 64;
    int k8   = (rem % 64) * 8;
    const float* base = ((k8 < 256) ? Wl : Wr) + (long)p * 65536;
    int kk = k8 & 255;
    __align__(16) __nv_bfloat16 h[8], l[8];
#pragma unroll
    for (int j = 0; j < 8; j++) {
        float v = __ldg(&base[(long)(kk + j) * 256 + nrow]);
        bsplit(v, h[j], l[j]);
    }
    long o = ((long)p * 256 + nrow) * 512 + k8;
    *(uint4*)(g_Whi + o) = *(const uint4*)h;
    *(uint4*)(g_Wlo + o) = *(const uint4*)l;
}

// ---- mma.sync fused SAGE GEMM -----------------------------------------------------
// A-tile producer fused with format conversion: LDG fp32 (g_agg or Xsrc),
// apply mean (1/deg) or relu, bf16 hi/lo split in registers, STS to SMEM.
#define A_STRIDE 144
#define A_BLK    (64 * 144)
#define B_OFF    36864
#define B_BLK    (256 * 144)
#define CADD_OFF 184320
#define CVG_OFF  185344
#define RED_OFF  186368
#define SMEM_SZ  187392

__global__ __launch_bounds__(256, 1) void mma_sage(
    const float* __restrict__ Xsrc,
    const __nv_bfloat16* __restrict__ Wh, const __nv_bfloat16* __restrict__ Wlo_,
    const float* __restrict__ bias, const float* __restrict__ cvA,
    const float* __restrict__ cvG,
    float* __restrict__ Out, long degoff, int n, int accum,
    int nagg, int nx, int reluX) {
    extern __shared__ char smem[];
    const int tid = threadIdx.x;
    const int lane = tid & 31, wid = tid >> 5;
    const int wm = wid >> 2, wn = wid & 3;
    const uint32_t sbase = smem_u32(smem);
    float* cadd   = (float*)(smem + CADD_OFF);
    float* cvgS   = (float*)(smem + CVG_OFF);
    float* rowred = (float*)(smem + RED_OFF);

    cadd[tid] = bias[tid] + (cvA ? cvA[tid] : 0.f);
    cvgS[tid] = cvG ? cvG[tid] : 0.f;

    const long row0 = (long)blockIdx.x * 64;
    const int nch = nagg + nx;

    float C[2][8][4];
#pragma unroll
    for (int mt = 0; mt < 2; mt++)
#pragma unroll
        for (int nt = 0; nt < 8; nt++)
#pragma unroll
            for (int q = 0; q < 4; q++) C[mt][nt][q] = 0.f;

    // A producer mapping: thread -> (row, 16-col segment)
    const int arow = tid >> 2, aq = tid & 3;
    const long agrow = row0 + arow;
    const bool aval = agrow < n;
    const float invm = aval ? (1.0f / fmaxf((float)g_deg[degoff + agrow], 1.0f)) : 0.f;

    auto issue = [&](int s, int c) {
        int kcol, wcol;
        const float* src;
        if (c < nagg) { src = g_agg; kcol = c * 64; wcol = c * 64; }
        else          { src = Xsrc;  kcol = (c - nagg) * 64; wcol = 256 + (c - nagg) * 64; }
        // A: 16 fp32 per thread -> bf16 hi/lo
        float vv[16];
        if (aval) {
            const float4* p = (const float4*)(src + agrow * 256 + kcol + aq * 16);
#pragma unroll
            for (int j = 0; j < 4; j++) {
                float4 f = __ldg(&p[j]);
                vv[j * 4 + 0] = f.x; vv[j * 4 + 1] = f.y;
                vv[j * 4 + 2] = f.z; vv[j * 4 + 3] = f.w;
            }
            if (c < nagg) {
#pragma unroll
                for (int j = 0; j < 16; j++) vv[j] *= invm;
            } else if (reluX) {
#pragma unroll
                for (int j = 0; j < 16; j++) vv[j] = fmaxf(vv[j], 0.f);
            }
        } else {
#pragma unroll
            for (int j = 0; j < 16; j++) vv[j] = 0.f;
        }
        __align__(16) __nv_bfloat16 h[16], l[16];
#pragma unroll
        for (int j = 0; j < 16; j++) bsplit(vv[j], h[j], l[j]);
        uint32_t ah_addr = sbase + (uint32_t)(s * 2) * A_BLK + arow * A_STRIDE + aq * 32;
        uint4 H0 = ((const uint4*)h)[0], H1 = ((const uint4*)h)[1];
        uint4 L0 = ((const uint4*)l)[0], L1 = ((const uint4*)l)[1];
        STS128(ah_addr,              H0.x, H0.y, H0.z, H0.w);
        STS128(ah_addr + 16,         H1.x, H1.y, H1.z, H1.w);
        STS128(ah_addr + A_BLK,      L0.x, L0.y, L0.z, L0.w);
        STS128(ah_addr + A_BLK + 16, L1.x, L1.y, L1.z, L1.w);
        // B: 256 rows x 64 bf16, both variants; 1 thread/row (cp.async)
#pragma unroll
        for (int v = 0; v < 2; v++) {
            const __nv_bfloat16* b = (v ? Wlo_ : Wh) + (long)tid * 512 + wcol;
            uint32_t bdst = sbase + B_OFF + (uint32_t)(s * 2 + v) * B_BLK + tid * A_STRIDE;
#pragma unroll
            for (int j = 0; j < 8; j++) cp16(bdst + j * 16, b + j * 8, 16);
        }
        CP_COMMIT();
    };

    issue(0, 0);
    if (nch > 1) issue(1, 1);

    const int a_r  = wm * 32 + (lane & 15);
    const int a_k8 = ((lane >> 4) & 1) * 8;
    const int b_n  = ((lane >> 4) & 1) * 8 + (lane & 7);
    const int b_k8 = ((lane >> 3) & 1) * 8;

    for (int c = 0; c < nch; c++) {
        if (c + 1 < nch) { CP_WAIT(1); } else { CP_WAIT(0); }
        __syncthreads();
        const int s = c & 1;
        const uint32_t aBase = sbase + (uint32_t)(s * 2) * A_BLK;
        const uint32_t bBase = sbase + B_OFF + (uint32_t)(s * 2) * B_BLK;

#pragma unroll
        for (int k16 = 0; k16 < 4; k16++) {
            const int kb = k16 * 16;
            uint32_t ah[2][4], al[2][4], bh[8][2], bl[8][2];
#pragma unroll
            for (int mt = 0; mt < 2; mt++) {
                uint32_t ad = aBase + (a_r + mt * 16) * A_STRIDE + (kb + a_k8) * 2;
                LDSM4(ah[mt][0], ah[mt][1], ah[mt][2], ah[mt][3], ad);
                LDSM4(al[mt][0], al[mt][1], al[mt][2], al[mt][3], ad + A_BLK);
            }
#pragma unroll
            for (int np = 0; np < 4; np++) {
                uint32_t bd = bBase + (wn * 64 + np * 16 + b_n) * A_STRIDE + (kb + b_k8) * 2;
                LDSM4(bh[np*2][0], bh[np*2][1], bh[np*2+1][0], bh[np*2+1][1], bd);
                LDSM4(bl[np*2][0], bl[np*2][1], bl[np*2+1][0], bl[np*2+1][1], bd + B_BLK);
            }
#pragma unroll
            for (int mt = 0; mt < 2; mt++)
#pragma unroll
                for (int nt = 0; nt < 8; nt++) {
                    MMA16816(C[mt][nt], ah[mt], bh[nt]);
                    MMA16816(C[mt][nt], al[mt], bh[nt]);
                    MMA16816(C[mt][nt], ah[mt], bl[nt]);
                }
        }
        __syncthreads();
        if (c + 2 < nch) issue(s, c + 2);
    }

    // ---- epilogue: + const, row L2 norm, accumulate store ----
    float gate_lo[2], gate_hi[2];
#pragma unroll
    for (int mt = 0; mt < 2; mt++) {
        int rl = wm * 32 + mt * 16 + (lane >> 2);
        long grl = row0 + rl, grh = grl + 8;
        gate_lo[mt] = (cvG && grl < n) ? ((g_deg[degoff + grl] > 0) ? 1.f : 0.f) : 0.f;
        gate_hi[mt] = (cvG && grh < n) ? ((g_deg[degoff + grh] > 0) ? 1.f : 0.f) : 0.f;
    }
    float s_lo[2] = {0.f, 0.f}, s_hi[2] = {0.f, 0.f};
#pragma unroll
    for (int mt = 0; mt < 2; mt++)
#pragma unroll
        for (int nt = 0; nt < 8; nt++) {
            int col = wn * 64 + nt * 8 + (lane & 3) * 2;
            float c0 = cadd[col], c1 = cadd[col + 1];
            float g0 = cvgS[col], g1 = cvgS[col + 1];
            float v0 = C[mt][nt][0] + c0 + gate_lo[mt] * g0;
            float v1 = C[mt][nt][1] + c1 + gate_lo[mt] * g1;
            float v2 = C[mt][nt][2] + c0 + gate_hi[mt] * g0;
            float v3 = C[mt][nt][3] + c1 + gate_hi[mt] * g1;
            C[mt][nt][0] = v0; C[mt][nt][1] = v1; C[mt][nt][2] = v2; C[mt][nt][3] = v3;
            s_lo[mt] += v0 * v0 + v1 * v1;
            s_hi[mt] += v2 * v2 + v3 * v3;
        }
#pragma unroll
    for (int mt = 0; mt < 2; mt++) {
        s_lo[mt] += __shfl_xor_sync(0xffffffffu, s_lo[mt], 1);
        s_lo[mt] += __shfl_xor_sync(0xffffffffu, s_lo[mt], 2);
        s_hi[mt] += __shfl_xor_sync(0xffffffffu, s_hi[mt], 1);
        s_hi[mt] += __shfl_xor_sync(0xffffffffu, s_hi[mt], 2);
    }
    if ((lane & 3) == 0) {
#pragma unroll
        for (int mt = 0; mt < 2; mt++) {
            int rl = wm * 32 + mt * 16 + (lane >> 2);
            rowred[wn * 64 + rl]     = s_lo[mt];
            rowred[wn * 64 + rl + 8] = s_hi[mt];
        }
    }
    __syncthreads();
#pragma unroll
    for (int mt = 0; mt < 2; mt++) {
        int rl = wm * 32 + mt * 16 + (lane >> 2);
        int rh = rl + 8;
        float ssl = rowred[rl] + rowred[64 + rl] + rowred[128 + rl] + rowred[192 + rl];
        float ssh = rowred[rh] + rowred[64 + rh] + rowred[128 + rh] + rowred[192 + rh];
        float scl = 1.0f / fmaxf(sqrtf(ssl), 1e-12f);
        float sch = 1.0f / fmaxf(sqrtf(ssh), 1e-12f);
        long grl = row0 + rl, grh = row0 + rh;
#pragma unroll
        for (int nt = 0; nt < 8; nt++) {
            int col = wn * 64 + nt * 8 + (lane & 3) * 2;
            if (grl < n) {
                float2 o = make_float2(C[mt][nt][0] * scl, C[mt][nt][1] * scl);
                float* op = Out + grl * 256 + col;
                if (accum) { float2 u = *(const float2*)op; o.x += u.x; o.y += u.y; }
                *(float2*)op = o;
            }
            if (grh < n) {
                float2 o = make_float2(C[mt][nt][2] * sch, C[mt][nt][3] * sch);
                float* op = Out + grh * 256 + col;
                if (accum) { float2 u = *(const float2*)op; o.x += u.x; o.y += u.y; }
                *(float2*)op = o;
            }
        }
    }
}

// ---- final head: relu(x_reaction) @ W_out[256x128] + b_out -----------------------
__global__ __launch_bounds__(256, 2) void final_gemm(
    int asel, long aoff, const float* __restrict__ W,
    const float* __restrict__ bias, float* __restrict__ C, int n) {
    __shared__ float As[16][64];
    __shared__ float Bs[16][128];
    const int tid = threadIdx.x;
    const long row0 = (long)blockIdx.x * 64;
    const int m = tid & 63, kq = tid >> 6;
    const int jb = tid & 31, kb2 = tid >> 5;
    const int tcol = tid & 31, tr = tid >> 5;

    const float* A = resolve_x(nullptr, asel, aoff);

    unsigned long long acc[8][2];
#pragma unroll
    for (int i = 0; i < 8; i++) { acc[i][0] = 0ULL; acc[i][1] = 0ULL; }

    const long arow = row0 + m;
    const bool aval = arow < n;

#pragma unroll 1
    for (int k0 = 0; k0 < 256; k0 += 16) {
        float4 av = make_float4(0.f, 0.f, 0.f, 0.f);
        if (aval) av = *(const float4*)&A[arow * DIM + k0 + kq * 4];
        av.x = fmaxf(av.x, 0.f); av.y = fmaxf(av.y, 0.f);
        av.z = fmaxf(av.z, 0.f); av.w = fmaxf(av.w, 0.f);
        float4 bv0 = *(const float4*)&W[(long)(k0 + kb2) * 128 + jb * 4];
        float4 bv1 = *(const float4*)&W[(long)(k0 + kb2 + 8) * 128 + jb * 4];
        __syncthreads();
        As[kq * 4 + 0][m] = av.x;
        As[kq * 4 + 1][m] = av.y;
        As[kq * 4 + 2][m] = av.z;
        As[kq * 4 + 3][m] = av.w;
        *(float4*)&Bs[kb2][jb * 4] = bv0;
        *(float4*)&Bs[kb2 + 8][jb * 4] = bv1;
        __syncthreads();
#pragma unroll
        for (int k = 0; k < 16; k++) {
            ulonglong2 b01 = *(const ulonglong2*)&Bs[k][tcol * 4];
            float4 a0 = *(const float4*)&As[k][tr * 8];
            float4 a1 = *(const float4*)&As[k][tr * 8 + 4];
            float aa[8] = {a0.x, a0.y, a0.z, a0.w, a1.x, a1.y, a1.z, a1.w};
#pragma unroll
            for (int i = 0; i < 8; i++) {
                unsigned long long a2v;
                PACK2(a2v, aa[i], aa[i]);
                FMA2(acc[i][0], a2v, b01.x);
                FMA2(acc[i][1], a2v, b01.y);
            }
        }
    }

    float4 bb = *(const float4*)&bias[tcol * 4];
    float bsv[4] = {bb.x, bb.y, bb.z, bb.w};
#pragma unroll
    for (int i = 0; i < 8; i++) {
        float v[4];
        UNPACK2(v[0], v[1], acc[i][0]);
        UNPACK2(v[2], v[3], acc[i][1]);
        long r = row0 + (long)tr * 8 + i;
        if (r < n) {
            float4 o0 = make_float4(v[0] + bsv[0], v[1] + bsv[1],
                                    v[2] + bsv[2], v[3] + bsv[3]);
            *(float4*)&C[r * 128 + tcol * 4] = o0;
        }
    }
}

// ---------------------------------------------------------------------------
extern "C" void kernel_launch(void* const* d_in, const int* in_sizes, int n_in,
                              void* d_out, int out_size) {
    const float* remb = (const float*)d_in[4];
    const float* cemb = (const float*)d_in[5];
    const float* ptab = (const float*)d_in[6];
    const float* mtab = (const float*)d_in[7];
    const float* Wl   = (const float*)d_in[8];
    const float* Wr   = (const float*)d_in[9];
    const float* bvec = (const float*)d_in[10];
    const float* Wout = (const float*)d_in[11];
    const float* bout = (const float*)d_in[12];
    const int* edge[7];
    int ecnt[7];
    for (int t = 0; t < 7; t++) {
        edge[t] = (const int*)d_in[13 + t];
        ecnt[t] = in_sizes[13 + t] / 2;
    }

    cudaFuncSetAttribute(mma_sage, cudaFuncAttributeMaxDynamicSharedMemorySize, SMEM_SZ);

    float *r1, *xA, *xB;
    __nv_bfloat16 *whi, *wlo;
    cudaGetSymbolAddress((void**)&r1, g_r1);
    cudaGetSymbolAddress((void**)&xA, g_xA);
    cudaGetSymbolAddress((void**)&xB, g_xB);
    cudaGetSymbolAddress((void**)&whi, g_Whi);
    cudaGetSymbolAddress((void**)&wlo, g_Wlo);

    // degrees
    zero_deg_kernel<<<(DEG_TOTAL + 255) / 256, 256>>>();
    for (int t = 0; t < 7; t++)
        deg_kernel<<<(ecnt[t] + 255) / 256, 256>>>(edge[t] + ecnt[t], ecnt[t], DEGOFF[t]);

    // weight repack
    conv_w_kernel<<<(int)((21L * 256 * 64 + 255) / 256), 256>>>(Wl, Wr);

    // layer-0 rank-1 vectors
    rank1_kernel<<<1, 256>>>(remb, Wr + 0 * 65536L, r1 + 0 * 256);
    rank1_kernel<<<1, 256>>>(remb, Wr + 1 * 65536L, r1 + 1 * 256);
    rank1_kernel<<<1, 256>>>(cemb, Wl + 2 * 65536L, r1 + 2 * 256);
    rank1_kernel<<<1, 256>>>(remb, Wr + 2 * 65536L, r1 + 3 * 256);
    rank1_kernel<<<1, 256>>>(cemb, Wr + 3 * 65536L, r1 + 4 * 256);
    rank1_kernel<<<1, 256>>>(cemb, Wr + 4 * 65536L, r1 + 5 * 256);
    rank1_kernel<<<1, 256>>>(remb, Wl + 5 * 65536L, r1 + 6 * 256);
    rank1_kernel<<<1, 256>>>(remb, Wl + 6 * 65536L, r1 + 7 * 256);
    t2_combine_kernel<<<1, 256>>>(r1 + 2 * 256, r1 + 3 * 256, bvec + 2 * 256);

    const float* src_ext[2] = {ptab, mtab};

    // ---------------- layer 0 ----------------
    for (int t = 0; t < 2; t++) {     // dst reaction: agg-only GEMM + const
        int nd = NNODE[0], e = ecnt[t];
        zero_agg_kernel<<<(int)(((long)nd * 64 + 255) / 256), 256>>>((long)nd * 64);
        scatter_kernel<<<(e * 32 + 255) / 256, 256>>>(src_ext[t], 2, 0, edge[t], edge[t] + e, e, 0);
        mma_sage<<<(nd + 63) / 64, 256, SMEM_SZ>>>(
            nullptr, whi + (long)t * 131072, wlo + (long)t * 131072,
            bvec + (long)t * 256, r1 + t * 256, nullptr,
            xB + XOFF[0] * DIM, DEGOFF[t], nd, t == 0 ? 0 : 1, 4, 0, 0);
    }
    t2_apply_kernel<<<(NNODE[0] * 64 + 255) / 256, 256>>>(xB + XOFF[0] * DIM, DEGOFF[2], NNODE[0]);
    for (int t = 3; t < 5; t++) {     // dst complex: agg-only GEMM + const
        int nd = NNODE[1], e = ecnt[t];
        zero_agg_kernel<<<(int)(((long)nd * 64 + 255) / 256), 256>>>((long)nd * 64);
        scatter_kernel<<<(e * 32 + 255) / 256, 256>>>(src_ext[t - 3], 2, 0, edge[t], edge[t] + e, e, 0);
        mma_sage<<<(nd + 63) / 64, 256, SMEM_SZ>>>(
            nullptr, whi + (long)t * 131072, wlo + (long)t * 131072,
            bvec + (long)t * 256, r1 + (t + 1) * 256, nullptr,
            xB + XOFF[1] * DIM, DEGOFF[t], nd, t == 3 ? 0 : 1, 4, 0, 0);
    }
    // t5: gate*vl + ptab@Wr (x-phase only), dst protein
    mma_sage<<<(NNODE[2] + 63) / 64, 256, SMEM_SZ>>>(
        ptab, whi + 5L * 131072, wlo + 5L * 131072,
        bvec + 5L * 256, nullptr, r1 + 6 * 256,
        xB + XOFF[2] * DIM, DEGOFF[5], NNODE[2], 0, 0, 4, 0);
    // t6: gate*vl + mtab@Wr, dst molecule
    mma_sage<<<(NNODE[3] + 63) / 64, 256, SMEM_SZ>>>(
        mtab, whi + 6L * 131072, wlo + 6L * 131072,
        bvec + 6L * 256, nullptr, r1 + 7 * 256,
        xB + XOFF[3] * DIM, DEGOFF[6], NNODE[3], 0, 0, 4, 0);

    // ---------------- layer 1 (reads xB -> writes xA) ----------------
    {
        bool first[4] = {true, true, true, true};
        for (int t = 0; t < 7; t++) {
            int s = ET_S[t], d = ET_D[t];
            int nd = NNODE[d], e = ecnt[t];
            zero_agg_kernel<<<(int)(((long)nd * 64 + 255) / 256), 256>>>((long)nd * 64);
            scatter_kernel<<<(e * 32 + 255) / 256, 256>>>(
                nullptr, 1, XOFF[s], edge[t], edge[t] + e, e, 1);
            mma_sage<<<(nd + 63) / 64, 256, SMEM_SZ>>>(
                xB + XOFF[d] * DIM,
                whi + (long)(7 + t) * 131072, wlo + (long)(7 + t) * 131072,
                bvec + (long)(7 + t) * 256, nullptr, nullptr,
                xA + XOFF[d] * DIM, DEGOFF[t], nd, first[d] ? 0 : 1, 4, 4, 1);
            first[d] = false;
        }
    }

    // ---------------- layer 2 (reads xA -> writes xB, dst reaction only) -------
    for (int t = 0; t < 3; t++) {
        int s = ET_S[t];
        int nd = NNODE[0], e = ecnt[t];
        zero_agg_kernel<<<(int)(((long)nd * 64 + 255) / 256), 256>>>((long)nd * 64);
        scatter_kernel<<<(e * 32 + 255) / 256, 256>>>(
            nullptr, 0, XOFF[s], edge[t], edge[t] + e, e, 1);
        mma_sage<<<(nd + 63) / 64, 256, SMEM_SZ>>>(
            xA + XOFF[0] * DIM,
            whi + (long)(14 + t) * 131072, wlo + (long)(14 + t) * 131072,
            bvec + (long)(14 + t) * 256, nullptr, nullptr,
            xB + XOFF[0] * DIM, DEGOFF[t], nd, t == 0 ? 0 : 1, 4, 4, 1);
    }

    // head: relu(x_reaction, in xB) @ W_out + b_out
    final_gemm<<<(NNODE[0] + 63) / 64, 256>>>(1, XOFF[0], Wout, bout, (float*)d_out, NNODE[0]);
}

// round 11
// speedup vs baseline: 1.6307x; 1.1778x over previous
#include <cuda_runtime.h>
#include <cuda_fp16.h>
#include <cstdint>

// ---------------------------------------------------------------------------
// HeteroGNN (3-layer hetero SAGE) on GB300 — Round 11.
//   R11 vs R10:
//   - MMA path: fp16 hi/lo 2-pass (Ah*Bh + Al*Bh) instead of bf16 3-pass.
//     B single fp16 => -33% MMA, half the B traffic, SMEM 187K -> 113K,
//     occupancy 1 -> 2.
//   - per-edge-type agg buffers (750k rows) + one fused scatter kernel per
//     layer + ranged zero kernels: ~60 -> ~41 launches.
// ---------------------------------------------------------------------------

#define DIM 256

static const int  NNODE[4]  = {100000, 50000, 200000, 150000};
static const long XOFF[4]   = {0, 100000, 150000, 350000};
static const int  ET_S[7]   = {2, 3, 1, 2, 3, 0, 0};
static const long DEGOFF[7] = {0, 100000, 200000, 300000, 350000, 400000, 600000};
#define DEG_TOTAL 750000

__device__ float  g_xA[128000000];
__device__ float  g_xB[128000000];
__device__ float  g_agg[192000000];          // 750k rows x 256 (per-type regions)
__device__ int    g_deg[DEG_TOTAL];
__device__ float  g_r1[8 * 256];
__device__ float  g_two[2 * 256];
__device__ __half g_W16[21 * 256 * 512];     // [pair][N=256][K=512] fp16

// ---- FFMA2 helpers (head GEMM) ---------------------------------------------
#define PACK2(out, lo, hi) \
    asm("mov.b64 %0, {%1, %2};" : "=l"(out) : "r"(__float_as_uint(lo)), "r"(__float_as_uint(hi)))
#define FMA2(acc, a, b) \
    asm("fma.rn.f32x2 %0, %1, %2, %0;" : "+l"(acc) : "l"(a), "l"(b))
#define UNPACK2(lo, hi, in) do { \
    unsigned _ul, _uh; \
    asm("mov.b64 {%0, %1}, %2;" : "=r"(_ul), "=r"(_uh) : "l"(in)); \
    lo = __uint_as_float(_ul); hi = __uint_as_float(_uh); } while (0)

__device__ __forceinline__ void red4(float* p, float4 v) {
    asm volatile("red.global.add.v4.f32 [%0], {%1,%2,%3,%4};"
                 :: "l"(p), "f"(v.x), "f"(v.y), "f"(v.z), "f"(v.w) : "memory");
}

// ---- mma.sync helpers ---------------------------------------------------------
__device__ __forceinline__ uint32_t smem_u32(const void* p) {
    uint32_t a;
    asm("{ .reg .u64 t; cvta.to.shared.u64 t, %1; cvt.u32.u64 %0, t; }" : "=r"(a) : "l"(p));
    return a;
}
__device__ __forceinline__ void cp16(uint32_t dst, const void* src, int sz) {
    asm volatile("cp.async.cg.shared.global [%0], [%1], 16, %2;"
                 :: "r"(dst), "l"(src), "r"(sz) : "memory");
}
#define CP_COMMIT() asm volatile("cp.async.commit_group;" ::: "memory")
#define CP_WAIT(N)  asm volatile("cp.async.wait_group %0;" :: "n"(N) : "memory")

#define LDSM4(r0, r1, r2, r3, addr) \
    asm volatile("ldmatrix.sync.aligned.m8n8.x4.shared.b16 {%0,%1,%2,%3}, [%4];" \
                 : "=r"(r0), "=r"(r1), "=r"(r2), "=r"(r3) : "r"(addr))

#define MMAF16(c, a, b) \
    asm volatile("mma.sync.aligned.m16n8k16.row.col.f32.f16.f16.f32 " \
                 "{%0,%1,%2,%3}, {%4,%5,%6,%7}, {%8,%9}, {%0,%1,%2,%3};" \
                 : "+f"((c)[0]), "+f"((c)[1]), "+f"((c)[2]), "+f"((c)[3]) \
                 : "r"((a)[0]), "r"((a)[1]), "r"((a)[2]), "r"((a)[3]), \
                   "r"((b)[0]), "r"((b)[1]))

#define STS128(ad, a, b, c, d) \
    asm volatile("st.shared.v4.b32 [%0], {%1, %2, %3, %4};" \
                 :: "r"(ad), "r"(a), "r"(b), "r"(c), "r"(d) : "memory")

__device__ __forceinline__ void hsplit(float v, __half& h, __half& l) {
    h = __float2half_rn(v);
    l = __float2half_rn(v - __half2float(h));
}

// ---- degree kernels -------------------------------------------------------------
__global__ void zero_deg_kernel() {
    int i = blockIdx.x * blockDim.x + threadIdx.x;
    if (i < DEG_TOTAL) g_deg[i] = 0;
}
__global__ void deg_kernel(const int* __restrict__ dstIdx, int e, long degOff) {
    int i = blockIdx.x * blockDim.x + threadIdx.x;
    if (i < e) atomicAdd(&g_deg[degOff + dstIdx[i]], 1);
}
__global__ void zero_range_kernel(long row0, long nrows) {
    long i = (long)blockIdx.x * blockDim.x + threadIdx.x;
    if (i < nrows * 64) ((float4*)(g_agg + row0 * DIM))[i] = make_float4(0.f, 0.f, 0.f, 0.f);
}

// ---- fused multi-type scatter ----------------------------------------------------
struct ScatP {
    const int*   srcIdx[7];
    const int*   dstIdx[7];
    const float* X[7];
    float*       agg[7];
    int e;
    int nt;
    int relu;
};
__global__ void scatter_fused(ScatP p) {
    int bpt = gridDim.x / p.nt;
    int ty  = blockIdx.x / bpt;
    long g  = (long)(blockIdx.x - ty * bpt) * blockDim.x + threadIdx.x;
    int w   = (int)(g >> 5);
    if (w >= p.e) return;
    int lane = (int)(g & 31);
    const float* X = p.X[ty];
    long s = p.srcIdx[ty][w];
    long d = p.dstIdx[ty][w];
    const float4* a = (const float4*)(X + s * DIM);
    float4 v0 = __ldg(&a[lane]);
    float4 v1 = __ldg(&a[lane + 32]);
    if (p.relu) {
        v0.x = fmaxf(v0.x, 0.f); v0.y = fmaxf(v0.y, 0.f);
        v0.z = fmaxf(v0.z, 0.f); v0.w = fmaxf(v0.w, 0.f);
        v1.x = fmaxf(v1.x, 0.f); v1.y = fmaxf(v1.y, 0.f);
        v1.z = fmaxf(v1.z, 0.f); v1.w = fmaxf(v1.w, 0.f);
    }
    float* o = p.agg[ty] + d * DIM;
    red4(o + lane * 4, v0);
    red4(o + 128 + lane * 4, v1);
}

// ---- misc small kernels -----------------------------------------------------------
__global__ void rank1_kernel(const float* __restrict__ v, const float* __restrict__ W,
                             float* __restrict__ out) {
    int j = threadIdx.x;
    float acc = 0.f;
#pragma unroll 8
    for (int k = 0; k < 256; k++) acc += __ldg(&v[k]) * __ldg(&W[k * 256 + j]);
    out[j] = acc;
}
__global__ void t2_combine_kernel(const float* __restrict__ vl, const float* __restrict__ vr,
                                  const float* __restrict__ b) {
    __shared__ float red[2][8];
    int j = threadIdx.x;
    float a0 = vr[j] + b[j];
    float a1 = a0 + vl[j];
    float s0 = a0 * a0, s1 = a1 * a1;
#pragma unroll
    for (int o = 16; o > 0; o >>= 1) {
        s0 += __shfl_xor_sync(0xffffffffu, s0, o);
        s1 += __shfl_xor_sync(0xffffffffu, s1, o);
    }
    if ((j & 31) == 0) { red[0][j >> 5] = s0; red[1][j >> 5] = s1; }
    __syncthreads();
    float t0 = 0.f, t1 = 0.f;
#pragma unroll
    for (int w = 0; w < 8; w++) { t0 += red[0][w]; t1 += red[1][w]; }
    g_two[j]       = a0 * (1.0f / fmaxf(sqrtf(t0), 1e-12f));
    g_two[256 + j] = a1 * (1.0f / fmaxf(sqrtf(t1), 1e-12f));
}
__global__ void t2_apply_kernel(float* __restrict__ Out, long degoff, int n) {
    long i = (long)blockIdx.x * blockDim.x + threadIdx.x;
    long r = i >> 6;
    int c = (int)(i & 63);
    if (r >= n) return;
    int gate = g_deg[degoff + r] > 0 ? 1 : 0;
    float4 w = ((const float4*)(g_two + gate * 256))[c];
    float4 u = ((float4*)(Out + r * DIM))[c];
    u.x += w.x; u.y += w.y; u.z += w.z; u.w += w.w;
    ((float4*)(Out + r * DIM))[c] = u;
}

// ---- weight repack: [pair][N=256][K=512] fp16 --------------------------------------
__global__ void conv_w_kernel(const float* __restrict__ Wl, const float* __restrict__ Wr) {
    long i = (long)blockIdx.x * blockDim.x + threadIdx.x;
    if (i >= 21L * 256 * 64) return;
    int p    = (int)(i / (256 * 64));
    int rem  = (int)(i % (256 * 64));
    int nrow = rem / 64;
    int k8   = (rem % 64) * 8;
    const float* base = ((k8 < 256) ? Wl : Wr) + (long)p * 65536;
    int kk = k8 & 255;
    __align__(16) __half h[8];
#pragma unroll
    for (int j = 0; j < 8; j++)
        h[j] = __float2half_rn(__ldg(&base[(long)(kk + j) * 256 + nrow]));
    *(uint4*)(g_W16 + ((long)p * 256 + nrow) * 512 + k8) = *(const uint4*)h;
}

// ---- mma.sync fused SAGE GEMM (fp16 hi/lo A, fp16 B, 2 passes) ----------------------
#define A_STRIDE 144
#define A_BLK    (64 * 144)          // 9216 B per (stage,var)
#define B_OFF    36864               // 4 * A_BLK
#define B_BLK    (256 * 144)         // 36864 B per stage
#define CADD_OFF 110592
#define CVG_OFF  111616
#define RED_OFF  112640
#define SMEM_SZ  113664

__global__ __launch_bounds__(256, 2) void mma_sage(
    const float* __restrict__ Asrc,            // per-type agg region (nagg chunks)
    const float* __restrict__ Xsrc,            // x rows (nx chunks)
    const __half* __restrict__ Wh,
    const float* __restrict__ bias, const float* __restrict__ cvA,
    const float* __restrict__ cvG,
    float* __restrict__ Out, long degoff, int n, int accum,
    int nagg, int nx, int reluX) {
    extern __shared__ char smem[];
    const int tid = threadIdx.x;
    const int lane = tid & 31, wid = tid >> 5;
    const int wm = wid >> 2, wn = wid & 3;
    const uint32_t sbase = smem_u32(smem);
    float* cadd   = (float*)(smem + CADD_OFF);
    float* cvgS   = (float*)(smem + CVG_OFF);
    float* rowred = (float*)(smem + RED_OFF);

    cadd[tid] = bias[tid] + (cvA ? cvA[tid] : 0.f);
    cvgS[tid] = cvG ? cvG[tid] : 0.f;

    const long row0 = (long)blockIdx.x * 64;
    const int nch = nagg + nx;

    float C[2][8][4];
#pragma unroll
    for (int mt = 0; mt < 2; mt++)
#pragma unroll
        for (int nt = 0; nt < 8; nt++)
#pragma unroll
            for (int q = 0; q < 4; q++) C[mt][nt][q] = 0.f;

    // A producer mapping: thread -> (row, 16-col segment)
    const int arow = tid >> 2, aq = tid & 3;
    const long agrow = row0 + arow;
    const bool aval = agrow < n;
    const float invm = aval ? (1.0f / fmaxf((float)g_deg[degoff + agrow], 1.0f)) : 0.f;

    auto issue = [&](int s, int c) {
        int kcol, wcol;
        const float* src;
        if (c < nagg) { src = Asrc; kcol = c * 64; wcol = c * 64; }
        else          { src = Xsrc; kcol = (c - nagg) * 64; wcol = 256 + (c - nagg) * 64; }
        float vv[16];
        if (aval) {
            const float4* p = (const float4*)(src + agrow * 256 + kcol + aq * 16);
#pragma unroll
            for (int j = 0; j < 4; j++) {
                float4 f = __ldg(&p[j]);
                vv[j * 4 + 0] = f.x; vv[j * 4 + 1] = f.y;
                vv[j * 4 + 2] = f.z; vv[j * 4 + 3] = f.w;
            }
            if (c < nagg) {
#pragma unroll
                for (int j = 0; j < 16; j++) vv[j] *= invm;
            } else if (reluX) {
#pragma unroll
                for (int j = 0; j < 16; j++) vv[j] = fmaxf(vv[j], 0.f);
            }
        } else {
#pragma unroll
            for (int j = 0; j < 16; j++) vv[j] = 0.f;
        }
        __align__(16) __half h[16], l[16];
#pragma unroll
        for (int j = 0; j < 16; j++) hsplit(vv[j], h[j], l[j]);
        uint32_t ah_addr = sbase + (uint32_t)(s * 2) * A_BLK + arow * A_STRIDE + aq * 32;
        uint4 H0 = ((const uint4*)h)[0], H1 = ((const uint4*)h)[1];
        uint4 L0 = ((const uint4*)l)[0], L1 = ((const uint4*)l)[1];
        STS128(ah_addr,              H0.x, H0.y, H0.z, H0.w);
        STS128(ah_addr + 16,         H1.x, H1.y, H1.z, H1.w);
        STS128(ah_addr + A_BLK,      L0.x, L0.y, L0.z, L0.w);
        STS128(ah_addr + A_BLK + 16, L1.x, L1.y, L1.z, L1.w);
        // B: 256 rows x 64 fp16; 1 thread/row (cp.async)
        const __half* b = Wh + (long)tid * 512 + wcol;
        uint32_t bdst = sbase + B_OFF + (uint32_t)s * B_BLK + tid * A_STRIDE;
#pragma unroll
        for (int j = 0; j < 8; j++) cp16(bdst + j * 16, b + j * 8, 16);
        CP_COMMIT();
    };

    issue(0, 0);
    if (nch > 1) issue(1, 1);

    const int a_r  = wm * 32 + (lane & 15);
    const int a_k8 = ((lane >> 4) & 1) * 8;
    const int b_n  = ((lane >> 4) & 1) * 8 + (lane & 7);
    const int b_k8 = ((lane >> 3) & 1) * 8;

    for (int c = 0; c < nch; c++) {
        if (c + 1 < nch) { CP_WAIT(1); } else { CP_WAIT(0); }
        __syncthreads();
        const int s = c & 1;
        const uint32_t aBase = sbase + (uint32_t)(s * 2) * A_BLK;
        const uint32_t bBase = sbase + B_OFF + (uint32_t)s * B_BLK;

#pragma unroll
        for (int k16 = 0; k16 < 4; k16++) {
            const int kb = k16 * 16;
            uint32_t ah[2][4], al[2][4], bh[8][2];
#pragma unroll
            for (int mt = 0; mt < 2; mt++) {
                uint32_t ad = aBase + (a_r + mt * 16) * A_STRIDE + (kb + a_k8) * 2;
                LDSM4(ah[mt][0], ah[mt][1], ah[mt][2], ah[mt][3], ad);
                LDSM4(al[mt][0], al[mt][1], al[mt][2], al[mt][3], ad + A_BLK);
            }
#pragma unroll
            for (int np = 0; np < 4; np++) {
                uint32_t bd = bBase + (wn * 64 + np * 16 + b_n) * A_STRIDE + (kb + b_k8) * 2;
                LDSM4(bh[np*2][0], bh[np*2][1], bh[np*2+1][0], bh[np*2+1][1], bd);
            }
#pragma unroll
            for (int mt = 0; mt < 2; mt++)
#pragma unroll
                for (int nt = 0; nt < 8; nt++) {
                    MMAF16(C[mt][nt], ah[mt], bh[nt]);
                    MMAF16(C[mt][nt], al[mt], bh[nt]);
                }
        }
        __syncthreads();
        if (c + 2 < nch) issue(s, c + 2);
    }

    // ---- epilogue: + const, row L2 norm, accumulate store ----
    float gate_lo[2], gate_hi[2];
#pragma unroll
    for (int mt = 0; mt < 2; mt++) {
        int rl = wm * 32 + mt * 16 + (lane >> 2);
        long grl = row0 + rl, grh = grl + 8;
        gate_lo[mt] = (cvG && grl < n) ? ((g_deg[degoff + grl] > 0) ? 1.f : 0.f) : 0.f;
        gate_hi[mt] = (cvG && grh < n) ? ((g_deg[degoff + grh] > 0) ? 1.f : 0.f) : 0.f;
    }
    float s_lo[2] = {0.f, 0.f}, s_hi[2] = {0.f, 0.f};
#pragma unroll
    for (int mt = 0; mt < 2; mt++)
#pragma unroll
        for (int nt = 0; nt < 8; nt++) {
            int col = wn * 64 + nt * 8 + (lane & 3) * 2;
            float c0 = cadd[col], c1 = cadd[col + 1];
            float g0 = cvgS[col], g1 = cvgS[col + 1];
            float v0 = C[mt][nt][0] + c0 + gate_lo[mt] * g0;
            float v1 = C[mt][nt][1] + c1 + gate_lo[mt] * g1;
            float v2 = C[mt][nt][2] + c0 + gate_hi[mt] * g0;
            float v3 = C[mt][nt][3] + c1 + gate_hi[mt] * g1;
            C[mt][nt][0] = v0; C[mt][nt][1] = v1; C[mt][nt][2] = v2; C[mt][nt][3] = v3;
            s_lo[mt] += v0 * v0 + v1 * v1;
            s_hi[mt] += v2 * v2 + v3 * v3;
        }
#pragma unroll
    for (int mt = 0; mt < 2; mt++) {
        s_lo[mt] += __shfl_xor_sync(0xffffffffu, s_lo[mt], 1);
        s_lo[mt] += __shfl_xor_sync(0xffffffffu, s_lo[mt], 2);
        s_hi[mt] += __shfl_xor_sync(0xffffffffu, s_hi[mt], 1);
        s_hi[mt] += __shfl_xor_sync(0xffffffffu, s_hi[mt], 2);
    }
    if ((lane & 3) == 0) {
#pragma unroll
        for (int mt = 0; mt < 2; mt++) {
            int rl = wm * 32 + mt * 16 + (lane >> 2);
            rowred[wn * 64 + rl]     = s_lo[mt];
            rowred[wn * 64 + rl + 8] = s_hi[mt];
        }
    }
    __syncthreads();
#pragma unroll
    for (int mt = 0; mt < 2; mt++) {
        int rl = wm * 32 + mt * 16 + (lane >> 2);
        int rh = rl + 8;
        float ssl = rowred[rl] + rowred[64 + rl] + rowred[128 + rl] + rowred[192 + rl];
        float ssh = rowred[rh] + rowred[64 + rh] + rowred[128 + rh] + rowred[192 + rh];
        float scl = 1.0f / fmaxf(sqrtf(ssl), 1e-12f);
        float sch = 1.0f / fmaxf(sqrtf(ssh), 1e-12f);
        long grl = row0 + rl, grh = row0 + rh;
#pragma unroll
        for (int nt = 0; nt < 8; nt++) {
            int col = wn * 64 + nt * 8 + (lane & 3) * 2;
            if (grl < n) {
                float2 o = make_float2(C[mt][nt][0] * scl, C[mt][nt][1] * scl);
                float* op = Out + grl * 256 + col;
                if (accum) { float2 u = *(const float2*)op; o.x += u.x; o.y += u.y; }
                *(float2*)op = o;
            }
            if (grh < n) {
                float2 o = make_float2(C[mt][nt][2] * sch, C[mt][nt][3] * sch);
                float* op = Out + grh * 256 + col;
                if (accum) { float2 u = *(const float2*)op; o.x += u.x; o.y += u.y; }
                *(float2*)op = o;
            }
        }
    }
}

// ---- final head: relu(x_reaction) @ W_out[256x128] + b_out -------------------------
__global__ __launch_bounds__(256, 2) void final_gemm(
    const float* __restrict__ A, const float* __restrict__ W,
    const float* __restrict__ bias, float* __restrict__ C, int n) {
    __shared__ float As[16][64];
    __shared__ float Bs[16][128];
    const int tid = threadIdx.x;
    const long row0 = (long)blockIdx.x * 64;
    const int m = tid & 63, kq = tid >> 6;
    const int jb = tid & 31, kb2 = tid >> 5;
    const int tcol = tid & 31, tr = tid >> 5;

    unsigned long long acc[8][2];
#pragma unroll
    for (int i = 0; i < 8; i++) { acc[i][0] = 0ULL; acc[i][1] = 0ULL; }

    const long arow = row0 + m;
    const bool aval = arow < n;

#pragma unroll 1
    for (int k0 = 0; k0 < 256; k0 += 16) {
        float4 av = make_float4(0.f, 0.f, 0.f, 0.f);
        if (aval) av = *(const float4*)&A[arow * DIM + k0 + kq * 4];
        av.x = fmaxf(av.x, 0.f); av.y = fmaxf(av.y, 0.f);
        av.z = fmaxf(av.z, 0.f); av.w = fmaxf(av.w, 0.f);
        float4 bv0 = *(const float4*)&W[(long)(k0 + kb2) * 128 + jb * 4];
        float4 bv1 = *(const float4*)&W[(long)(k0 + kb2 + 8) * 128 + jb * 4];
        __syncthreads();
        As[kq * 4 + 0][m] = av.x;
        As[kq * 4 + 1][m] = av.y;
        As[kq * 4 + 2][m] = av.z;
        As[kq * 4 + 3][m] = av.w;
        *(float4*)&Bs[kb2][jb * 4] = bv0;
        *(float4*)&Bs[kb2 + 8][jb * 4] = bv1;
        __syncthreads();
#pragma unroll
        for (int k = 0; k < 16; k++) {
            ulonglong2 b01 = *(const ulonglong2*)&Bs[k][tcol * 4];
            float4 a0 = *(const float4*)&As[k][tr * 8];
            float4 a1 = *(const float4*)&As[k][tr * 8 + 4];
            float aa[8] = {a0.x, a0.y, a0.z, a0.w, a1.x, a1.y, a1.z, a1.w};
#pragma unroll
            for (int i = 0; i < 8; i++) {
                unsigned long long a2v;
                PACK2(a2v, aa[i], aa[i]);
                FMA2(acc[i][0], a2v, b01.x);
                FMA2(acc[i][1], a2v, b01.y);
            }
        }
    }

    float4 bb = *(const float4*)&bias[tcol * 4];
    float bsv[4] = {bb.x, bb.y, bb.z, bb.w};
#pragma unroll
    for (int i = 0; i < 8; i++) {
        float v[4];
        UNPACK2(v[0], v[1], acc[i][0]);
        UNPACK2(v[2], v[3], acc[i][1]);
        long r = row0 + (long)tr * 8 + i;
        if (r < n) {
            float4 o0 = make_float4(v[0] + bsv[0], v[1] + bsv[1],
                                    v[2] + bsv[2], v[3] + bsv[3]);
            *(float4*)&C[r * 128 + tcol * 4] = o0;
        }
    }
}

// ---------------------------------------------------------------------------
extern "C" void kernel_launch(void* const* d_in, const int* in_sizes, int n_in,
                              void* d_out, int out_size) {
    const float* remb = (const float*)d_in[4];
    const float* cemb = (const float*)d_in[5];
    const float* ptab = (const float*)d_in[6];
    const float* mtab = (const float*)d_in[7];
    const float* Wl   = (const float*)d_in[8];
    const float* Wr   = (const float*)d_in[9];
    const float* bvec = (const float*)d_in[10];
    const float* Wout = (const float*)d_in[11];
    const float* bout = (const float*)d_in[12];
    const int* edge[7];
    int ecnt[7];
    for (int t = 0; t < 7; t++) {
        edge[t] = (const int*)d_in[13 + t];
        ecnt[t] = in_sizes[13 + t] / 2;
    }
    const int E = ecnt[0];                     // uniform (300000)
    const int BPT = (E * 32 + 255) / 256;      // blocks per type in fused scatter

    cudaFuncSetAttribute(mma_sage, cudaFuncAttributeMaxDynamicSharedMemorySize, SMEM_SZ);

    float *r1, *xA, *xB, *agg;
    __half* w16;
    cudaGetSymbolAddress((void**)&r1, g_r1);
    cudaGetSymbolAddress((void**)&xA, g_xA);
    cudaGetSymbolAddress((void**)&xB, g_xB);
    cudaGetSymbolAddress((void**)&agg, g_agg);
    cudaGetSymbolAddress((void**)&w16, g_W16);

    // degrees
    zero_deg_kernel<<<(DEG_TOTAL + 255) / 256, 256>>>();
    for (int t = 0; t < 7; t++)
        deg_kernel<<<(ecnt[t] + 255) / 256, 256>>>(edge[t] + ecnt[t], ecnt[t], DEGOFF[t]);

    // weight repack + rank-1 vectors
    conv_w_kernel<<<(int)((21L * 256 * 64 + 255) / 256), 256>>>(Wl, Wr);
    rank1_kernel<<<1, 256>>>(remb, Wr + 0 * 65536L, r1 + 0 * 256);
    rank1_kernel<<<1, 256>>>(remb, Wr + 1 * 65536L, r1 + 1 * 256);
    rank1_kernel<<<1, 256>>>(cemb, Wl + 2 * 65536L, r1 + 2 * 256);
    rank1_kernel<<<1, 256>>>(remb, Wr + 2 * 65536L, r1 + 3 * 256);
    rank1_kernel<<<1, 256>>>(cemb, Wr + 3 * 65536L, r1 + 4 * 256);
    rank1_kernel<<<1, 256>>>(cemb, Wr + 4 * 65536L, r1 + 5 * 256);
    rank1_kernel<<<1, 256>>>(remb, Wl + 5 * 65536L, r1 + 6 * 256);
    rank1_kernel<<<1, 256>>>(remb, Wl + 6 * 65536L, r1 + 7 * 256);
    t2_combine_kernel<<<1, 256>>>(r1 + 2 * 256, r1 + 3 * 256, bvec + 2 * 256);

    // ---------------- layer 0 ----------------
    // zero agg regions for types 0,1 ([0,200k)) and 3,4 ([300k,400k))
    zero_range_kernel<<<(int)((200000L * 64 + 255) / 256), 256>>>(0, 200000);
    zero_range_kernel<<<(int)((100000L * 64 + 255) / 256), 256>>>(300000, 100000);
    {   // fused scatter: types 0,1,3,4 (sources ptab/mtab, no relu)
        ScatP p{};
        const int ts[4] = {0, 1, 3, 4};
        const float* xs[4] = {ptab, mtab, ptab, mtab};
        for (int i = 0; i < 4; i++) {
            int t = ts[i];
            p.srcIdx[i] = edge[t];
            p.dstIdx[i] = edge[t] + ecnt[t];
            p.X[i] = xs[i];
            p.agg[i] = agg + DEGOFF[t] * DIM;
        }
        p.e = E; p.nt = 4; p.relu = 0;
        scatter_fused<<<BPT * 4, 256>>>(p);
    }
    for (int t = 0; t < 2; t++)       // dst reaction: agg-only GEMM + const
        mma_sage<<<(NNODE[0] + 63) / 64, 256, SMEM_SZ>>>(
            agg + DEGOFF[t] * DIM, nullptr, w16 + (long)t * 131072,
            bvec + (long)t * 256, r1 + t * 256, nullptr,
            xB + XOFF[0] * DIM, DEGOFF[t], NNODE[0], t == 0 ? 0 : 1, 4, 0, 0);
    t2_apply_kernel<<<(NNODE[0] * 64 + 255) / 256, 256>>>(xB + XOFF[0] * DIM, DEGOFF[2], NNODE[0]);
    for (int t = 3; t < 5; t++)       // dst complex: agg-only GEMM + const
        mma_sage<<<(NNODE[1] + 63) / 64, 256, SMEM_SZ>>>(
            agg + DEGOFF[t] * DIM, nullptr, w16 + (long)t * 131072,
            bvec + (long)t * 256, r1 + (t + 1) * 256, nullptr,
            xB + XOFF[1] * DIM, DEGOFF[t], NNODE[1], t == 3 ? 0 : 1, 4, 0, 0);
    // t5: gate*vl + ptab@Wr (x-phase only), dst protein
    mma_sage<<<(NNODE[2] + 63) / 64, 256, SMEM_SZ>>>(
        nullptr, ptab, w16 + 5L * 131072,
        bvec + 5L * 256, nullptr, r1 + 6 * 256,
        xB + XOFF[2] * DIM, DEGOFF[5], NNODE[2], 0, 0, 4, 0);
    // t6: gate*vl + mtab@Wr, dst molecule
    mma_sage<<<(NNODE[3] + 63) / 64, 256, SMEM_SZ>>>(
        nullptr, mtab, w16 + 6L * 131072,
        bvec + 6L * 256, nullptr, r1 + 7 * 256,
        xB + XOFF[3] * DIM, DEGOFF[6], NNODE[3], 0, 0, 4, 0);

    // ---------------- layer 1 (reads xB -> writes xA) ----------------
    zero_range_kernel<<<(int)((750000L * 64 + 255) / 256), 256>>>(0, 750000);
    {   // fused scatter: all 7 types from xB, relu
        ScatP p{};
        for (int t = 0; t < 7; t++) {
            p.srcIdx[t] = edge[t];
            p.dstIdx[t] = edge[t] + ecnt[t];
            p.X[t] = xB + XOFF[ET_S[t]] * DIM;
            p.agg[t] = agg + DEGOFF[t] * DIM;
        }
        p.e = E; p.nt = 7; p.relu = 1;
        scatter_fused<<<BPT * 7, 256>>>(p);
    }
    {
        const int  DN[7]  = {0, 0, 0, 1, 1, 2, 3};
        bool first[4] = {true, true, true, true};
        for (int t = 0; t < 7; t++) {
            int d = DN[t];
            mma_sage<<<(NNODE[d] + 63) / 64, 256, SMEM_SZ>>>(
                agg + DEGOFF[t] * DIM, xB + XOFF[d] * DIM,
                w16 + (long)(7 + t) * 131072,
                bvec + (long)(7 + t) * 256, nullptr, nullptr,
                xA + XOFF[d] * DIM, DEGOFF[t], NNODE[d], first[d] ? 0 : 1, 4, 4, 1);
            first[d] = false;
        }
    }

    // ---------------- layer 2 (reads xA -> writes xB, dst reaction only) -------
    zero_range_kernel<<<(int)((300000L * 64 + 255) / 256), 256>>>(0, 300000);
    {   // fused scatter: types 0,1,2 from xA, relu
        ScatP p{};
        for (int t = 0; t < 3; t++) {
            p.srcIdx[t] = edge[t];
            p.dstIdx[t] = edge[t] + ecnt[t];
            p.X[t] = xA + XOFF[ET_S[t]] * DIM;
            p.agg[t] = agg + DEGOFF[t] * DIM;
        }
        p.e = E; p.nt = 3; p.relu = 1;
        scatter_fused<<<BPT * 3, 256>>>(p);
    }
    for (int t = 0; t < 3; t++)
        mma_sage<<<(NNODE[0] + 63) / 64, 256, SMEM_SZ>>>(
            agg + DEGOFF[t] * DIM, xA + XOFF[0] * DIM,
            w16 + (long)(14 + t) * 131072,
            bvec + (long)(14 + t) * 256, nullptr, nullptr,
            xB + XOFF[0] * DIM, DEGOFF[t], NNODE[0], t == 0 ? 0 : 1, 4, 4, 1);

    // head: relu(x_reaction, in xB) @ W_out + b_out
    final_gemm<<<(NNODE[0] + 63) / 64, 256>>>(xB + XOFF[0] * DIM, Wout, bout,
                                              (float*)d_out, NNODE[0]);
}

// round 12
// speedup vs baseline: 2.2576x; 1.3845x over previous
#include <cuda_runtime.h>
#include <cuda_fp16.h>
#include <cstdint>

// ---------------------------------------------------------------------------
// HeteroGNN (3-layer hetero SAGE) on GB300 — Round 11.
//   R11 vs R10:
//   - MMA path: fp16 hi/lo 2-pass (Ah*Bh + Al*Bh) instead of bf16 3-pass.
//     B single fp16 => -33% MMA, half the B traffic, SMEM 187K -> 113K,
//     occupancy 1 -> 2.
//   - per-edge-type agg buffers (750k rows) + one fused scatter kernel per
//     layer + ranged zero kernels: ~60 -> ~41 launches.
// ---------------------------------------------------------------------------

#define DIM 256

static const int  NNODE[4]  = {100000, 50000, 200000, 150000};
static const long XOFF[4]   = {0, 100000, 150000, 350000};
static const int  ET_S[7]   = {2, 3, 1, 2, 3, 0, 0};
static const long DEGOFF[7] = {0, 100000, 200000, 300000, 350000, 400000, 600000};
#define DEG_TOTAL 750000

__device__ float  g_xA[128000000];
__device__ float  g_xB[128000000];
__device__ float  g_agg[192000000];          // 750k rows x 256 (per-type regions)
__device__ int    g_deg[DEG_TOTAL];
__device__ float  g_r1[8 * 256];
__device__ float  g_two[2 * 256];
__device__ __half g_W16[21 * 256 * 512];     // [pair][N=256][K=512] fp16

// ---- FFMA2 helpers (head GEMM) ---------------------------------------------
#define PACK2(out, lo, hi) \
    asm("mov.b64 %0, {%1, %2};" : "=l"(out) : "r"(__float_as_uint(lo)), "r"(__float_as_uint(hi)))
#define FMA2(acc, a, b) \
    asm("fma.rn.f32x2 %0, %1, %2, %0;" : "+l"(acc) : "l"(a), "l"(b))
#define UNPACK2(lo, hi, in) do { \
    unsigned _ul, _uh; \
    asm("mov.b64 {%0, %1}, %2;" : "=r"(_ul), "=r"(_uh) : "l"(in)); \
    lo = __uint_as_float(_ul); hi = __uint_as_float(_uh); } while (0)

__device__ __forceinline__ void red4(float* p, float4 v) {
    asm volatile("red.global.add.v4.f32 [%0], {%1,%2,%3,%4};"
                 :: "l"(p), "f"(v.x), "f"(v.y), "f"(v.z), "f"(v.w) : "memory");
}

// ---- mma.sync helpers ---------------------------------------------------------
__device__ __forceinline__ uint32_t smem_u32(const void* p) {
    uint32_t a;
    asm("{ .reg .u64 t; cvta.to.shared.u64 t, %1; cvt.u32.u64 %0, t; }" : "=r"(a) : "l"(p));
    return a;
}
__device__ __forceinline__ void cp16(uint32_t dst, const void* src, int sz) {
    asm volatile("cp.async.cg.shared.global [%0], [%1], 16, %2;"
                 :: "r"(dst), "l"(src), "r"(sz) : "memory");
}
#define CP_COMMIT() asm volatile("cp.async.commit_group;" ::: "memory")
#define CP_WAIT(N)  asm volatile("cp.async.wait_group %0;" :: "n"(N) : "memory")

#define LDSM4(r0, r1, r2, r3, addr) \
    asm volatile("ldmatrix.sync.aligned.m8n8.x4.shared.b16 {%0,%1,%2,%3}, [%4];" \
                 : "=r"(r0), "=r"(r1), "=r"(r2), "=r"(r3) : "r"(addr))

#define MMAF16(c, a, b) \
    asm volatile("mma.sync.aligned.m16n8k16.row.col.f32.f16.f16.f32 " \
                 "{%0,%1,%2,%3}, {%4,%5,%6,%7}, {%8,%9}, {%0,%1,%2,%3};" \
                 : "+f"((c)[0]), "+f"((c)[1]), "+f"((c)[2]), "+f"((c)[3]) \
                 : "r"((a)[0]), "r"((a)[1]), "r"((a)[2]), "r"((a)[3]), \
                   "r"((b)[0]), "r"((b)[1]))

#define STS128(ad, a, b, c, d) \
    asm volatile("st.shared.v4.b32 [%0], {%1, %2, %3, %4};" \
                 :: "r"(ad), "r"(a), "r"(b), "r"(c), "r"(d) : "memory")

__device__ __forceinline__ void hsplit(float v, __half& h, __half& l) {
    h = __float2half_rn(v);
    l = __float2half_rn(v - __half2float(h));
}

// ---- degree kernels -------------------------------------------------------------
__global__ void zero_deg_kernel() {
    int i = blockIdx.x * blockDim.x + threadIdx.x;
    if (i < DEG_TOTAL) g_deg[i] = 0;
}
__global__ void deg_kernel(const int* __restrict__ dstIdx, int e, long degOff) {
    int i = blockIdx.x * blockDim.x + threadIdx.x;
    if (i < e) atomicAdd(&g_deg[degOff + dstIdx[i]], 1);
}
__global__ void zero_range_kernel(long row0, long nrows) {
    long i = (long)blockIdx.x * blockDim.x + threadIdx.x;
    if (i < nrows * 64) ((float4*)(g_agg + row0 * DIM))[i] = make_float4(0.f, 0.f, 0.f, 0.f);
}

// ---- fused multi-type scatter ----------------------------------------------------
struct ScatP {
    const int*   srcIdx[7];
    const int*   dstIdx[7];
    const float* X[7];
    float*       agg[7];
    int e;
    int nt;
    int relu;
};
__global__ void scatter_fused(ScatP p) {
    int bpt = gridDim.x / p.nt;
    int ty  = blockIdx.x / bpt;
    long g  = (long)(blockIdx.x - ty * bpt) * blockDim.x + threadIdx.x;
    int w   = (int)(g >> 5);
    if (w >= p.e) return;
    int lane = (int)(g & 31);
    const float* X = p.X[ty];
    long s = p.srcIdx[ty][w];
    long d = p.dstIdx[ty][w];
    const float4* a = (const float4*)(X + s * DIM);
    float4 v0 = __ldg(&a[lane]);
    float4 v1 = __ldg(&a[lane + 32]);
    if (p.relu) {
        v0.x = fmaxf(v0.x, 0.f); v0.y = fmaxf(v0.y, 0.f);
        v0.z = fmaxf(v0.z, 0.f); v0.w = fmaxf(v0.w, 0.f);
        v1.x = fmaxf(v1.x, 0.f); v1.y = fmaxf(v1.y, 0.f);
        v1.z = fmaxf(v1.z, 0.f); v1.w = fmaxf(v1.w, 0.f);
    }
    float* o = p.agg[ty] + d * DIM;
    red4(o + lane * 4, v0);
    red4(o + 128 + lane * 4, v1);
}

// ---- misc small kernels -----------------------------------------------------------
__global__ void rank1_kernel(const float* __restrict__ v, const float* __restrict__ W,
                             float* __restrict__ out) {
    int j = threadIdx.x;
    float acc = 0.f;
#pragma unroll 8
    for (int k = 0; k < 256; k++) acc += __ldg(&v[k]) * __ldg(&W[k * 256 + j]);
    out[j] = acc;
}
__global__ void t2_combine_kernel(const float* __restrict__ vl, const float* __restrict__ vr,
                                  const float* __restrict__ b) {
    __shared__ float red[2][8];
    int j = threadIdx.x;
    float a0 = vr[j] + b[j];
    float a1 = a0 + vl[j];
    float s0 = a0 * a0, s1 = a1 * a1;
#pragma unroll
    for (int o = 16; o > 0; o >>= 1) {
        s0 += __shfl_xor_sync(0xffffffffu, s0, o);
        s1 += __shfl_xor_sync(0xffffffffu, s1, o);
    }
    if ((j & 31) == 0) { red[0][j >> 5] = s0; red[1][j >> 5] = s1; }
    __syncthreads();
    float t0 = 0.f, t1 = 0.f;
#pragma unroll
    for (int w = 0; w < 8; w++) { t0 += red[0][w]; t1 += red[1][w]; }
    g_two[j]       = a0 * (1.0f / fmaxf(sqrtf(t0), 1e-12f));
    g_two[256 + j] = a1 * (1.0f / fmaxf(sqrtf(t1), 1e-12f));
}
__global__ void t2_apply_kernel(float* __restrict__ Out, long degoff, int n) {
    long i = (long)blockIdx.x * blockDim.x + threadIdx.x;
    long r = i >> 6;
    int c = (int)(i & 63);
    if (r >= n) return;
    int gate = g_deg[degoff + r] > 0 ? 1 : 0;
    float4 w = ((const float4*)(g_two + gate * 256))[c];
    float4 u = ((float4*)(Out + r * DIM))[c];
    u.x += w.x; u.y += w.y; u.z += w.z; u.w += w.w;
    ((float4*)(Out + r * DIM))[c] = u;
}

// ---- weight repack: [pair][N=256][K=512] fp16 --------------------------------------
__global__ void conv_w_kernel(const float* __restrict__ Wl, const float* __restrict__ Wr) {
    long i = (long)blockIdx.x * blockDim.x + threadIdx.x;
    if (i >= 21L * 256 * 64) return;
    int p    = (int)(i / (256 * 64));
    int rem  = (int)(i % (256 * 64));
    int nrow = rem / 64;
    int k8   = (rem % 64) * 8;
    const float* base = ((k8 < 256) ? Wl : Wr) + (long)p * 65536;
    int kk = k8 & 255;
    __align__(16) __half h[8];
#pragma unroll
    for (int j = 0; j < 8; j++)
        h[j] = __float2half_rn(__ldg(&base[(long)(kk + j) * 256 + nrow]));
    *(uint4*)(g_W16 + ((long)p * 256 + nrow) * 512 + k8) = *(const uint4*)h;
}

// ---- mma.sync fused SAGE GEMM (fp16 hi/lo A, fp16 B, 2 passes) ----------------------
#define A_STRIDE 144
#define A_BLK    (64 * 144)          // 9216 B per (stage,var)
#define B_OFF    36864               // 4 * A_BLK
#define B_BLK    (256 * 144)         // 36864 B per stage
#define CADD_OFF 110592
#define CVG_OFF  111616
#define RED_OFF  112640
#define SMEM_SZ  113664

__global__ __launch_bounds__(256, 2) void mma_sage(
    const float* __restrict__ Asrc,            // per-type agg region (nagg chunks)
    const float* __restrict__ Xsrc,            // x rows (nx chunks)
    const __half* __restrict__ Wh,
    const float* __restrict__ bias, const float* __restrict__ cvA,
    const float* __restrict__ cvG,
    float* __restrict__ Out, long degoff, int n, int accum,
    int nagg, int nx, int reluX) {
    extern __shared__ char smem[];
    const int tid = threadIdx.x;
    const int lane = tid & 31, wid = tid >> 5;
    const int wm = wid >> 2, wn = wid & 3;
    const uint32_t sbase = smem_u32(smem);
    float* cadd   = (float*)(smem + CADD_OFF);
    float* cvgS   = (float*)(smem + CVG_OFF);
    float* rowred = (float*)(smem + RED_OFF);

    cadd[tid] = bias[tid] + (cvA ? cvA[tid] : 0.f);
    cvgS[tid] = cvG ? cvG[tid] : 0.f;

    const long row0 = (long)blockIdx.x * 64;
    const int nch = nagg + nx;

    float C[2][8][4];
#pragma unroll
    for (int mt = 0; mt < 2; mt++)
#pragma unroll
        for (int nt = 0; nt < 8; nt++)
#pragma unroll
            for (int q = 0; q < 4; q++) C[mt][nt][q] = 0.f;

    // A producer mapping: thread -> (row, 16-col segment)
    const int arow = tid >> 2, aq = tid & 3;
    const long agrow = row0 + arow;
    const bool aval = agrow < n;
    const float invm = aval ? (1.0f / fmaxf((float)g_deg[degoff + agrow], 1.0f)) : 0.f;

    auto issue = [&](int s, int c) {
        int kcol, wcol;
        const float* src;
        if (c < nagg) { src = Asrc; kcol = c * 64; wcol = c * 64; }
        else          { src = Xsrc; kcol = (c - nagg) * 64; wcol = 256 + (c - nagg) * 64; }
        float vv[16];
        if (aval) {
            const float4* p = (const float4*)(src + agrow * 256 + kcol + aq * 16);
#pragma unroll
            for (int j = 0; j < 4; j++) {
                float4 f = __ldg(&p[j]);
                vv[j * 4 + 0] = f.x; vv[j * 4 + 1] = f.y;
                vv[j * 4 + 2] = f.z; vv[j * 4 + 3] = f.w;
            }
            if (c < nagg) {
#pragma unroll
                for (int j = 0; j < 16; j++) vv[j] *= invm;
            } else if (reluX) {
#pragma unroll
                for (int j = 0; j < 16; j++) vv[j] = fmaxf(vv[j], 0.f);
            }
        } else {
#pragma unroll
            for (int j = 0; j < 16; j++) vv[j] = 0.f;
        }
        __align__(16) __half h[16], l[16];
#pragma unroll
        for (int j = 0; j < 16; j++) hsplit(vv[j], h[j], l[j]);
        uint32_t ah_addr = sbase + (uint32_t)(s * 2) * A_BLK + arow * A_STRIDE + aq * 32;
        uint4 H0 = ((const uint4*)h)[0], H1 = ((const uint4*)h)[1];
        uint4 L0 = ((const uint4*)l)[0], L1 = ((const uint4*)l)[1];
        STS128(ah_addr,              H0.x, H0.y, H0.z, H0.w);
        STS128(ah_addr + 16,         H1.x, H1.y, H1.z, H1.w);
        STS128(ah_addr + A_BLK,      L0.x, L0.y, L0.z, L0.w);
        STS128(ah_addr + A_BLK + 16, L1.x, L1.y, L1.z, L1.w);
        // B: 256 rows x 64 fp16; 1 thread/row (cp.async)
        const __half* b = Wh + (long)tid * 512 + wcol;
        uint32_t bdst = sbase + B_OFF + (uint32_t)s * B_BLK + tid * A_STRIDE;
#pragma unroll
        for (int j = 0; j < 8; j++) cp16(bdst + j * 16, b + j * 8, 16);
        CP_COMMIT();
    };

    issue(0, 0);
    if (nch > 1) issue(1, 1);

    const int a_r  = wm * 32 + (lane & 15);
    const int a_k8 = ((lane >> 4) & 1) * 8;
    const int b_n  = ((lane >> 4) & 1) * 8 + (lane & 7);
    const int b_k8 = ((lane >> 3) & 1) * 8;

    for (int c = 0; c < nch; c++) {
        if (c + 1 < nch) { CP_WAIT(1); } else { CP_WAIT(0); }
        __syncthreads();
        const int s = c & 1;
        const uint32_t aBase = sbase + (uint32_t)(s * 2) * A_BLK;
        const uint32_t bBase = sbase + B_OFF + (uint32_t)s * B_BLK;

#pragma unroll
        for (int k16 = 0; k16 < 4; k16++) {
            const int kb = k16 * 16;
            uint32_t ah[2][4], al[2][4], bh[8][2];
#pragma unroll
            for (int mt = 0; mt < 2; mt++) {
                uint32_t ad = aBase + (a_r + mt * 16) * A_STRIDE + (kb + a_k8) * 2;
                LDSM4(ah[mt][0], ah[mt][1], ah[mt][2], ah[mt][3], ad);
                LDSM4(al[mt][0], al[mt][1], al[mt][2], al[mt][3], ad + A_BLK);
            }
#pragma unroll
            for (int np = 0; np < 4; np++) {
                uint32_t bd = bBase + (wn * 64 + np * 16 + b_n) * A_STRIDE + (kb + b_k8) * 2;
                LDSM4(bh[np*2][0], bh[np*2][1], bh[np*2+1][0], bh[np*2+1][1], bd);
            }
#pragma unroll
            for (int mt = 0; mt < 2; mt++)
#pragma unroll
                for (int nt = 0; nt < 8; nt++) {
                    MMAF16(C[mt][nt], ah[mt], bh[nt]);
                    MMAF16(C[mt][nt], al[mt], bh[nt]);
                }
        }
        __syncthreads();
        if (c + 2 < nch) issue(s, c + 2);
    }

    // ---- epilogue: + const, row L2 norm, accumulate store ----
    float gate_lo[2], gate_hi[2];
#pragma unroll
    for (int mt = 0; mt < 2; mt++) {
        int rl = wm * 32 + mt * 16 + (lane >> 2);
        long grl = row0 + rl, grh = grl + 8;
        gate_lo[mt] = (cvG && grl < n) ? ((g_deg[degoff + grl] > 0) ? 1.f : 0.f) : 0.f;
        gate_hi[mt] = (cvG && grh < n) ? ((g_deg[degoff + grh] > 0) ? 1.f : 0.f) : 0.f;
    }
    float s_lo[2] = {0.f, 0.f}, s_hi[2] = {0.f, 0.f};
#pragma unroll
    for (int mt = 0; mt < 2; mt++)
#pragma unroll
        for (int nt = 0; nt < 8; nt++) {
            int col = wn * 64 + nt * 8 + (lane & 3) * 2;
            float c0 = cadd[col], c1 = cadd[col + 1];
            float g0 = cvgS[col], g1 = cvgS[col + 1];
            float v0 = C[mt][nt][0] + c0 + gate_lo[mt] * g0;
            float v1 = C[mt][nt][1] + c1 + gate_lo[mt] * g1;
            float v2 = C[mt][nt][2] + c0 + gate_hi[mt] * g0;
            float v3 = C[mt][nt][3] + c1 + gate_hi[mt] * g1;
            C[mt][nt][0] = v0; C[mt][nt][1] = v1; C[mt][nt][2] = v2; C[mt][nt][3] = v3;
            s_lo[mt] += v0 * v0 + v1 * v1;
            s_hi[mt] += v2 * v2 + v3 * v3;
        }
#pragma unroll
    for (int mt = 0; mt < 2; mt++) {
        s_lo[mt] += __shfl_xor_sync(0xffffffffu, s_lo[mt], 1);
        s_lo[mt] += __shfl_xor_sync(0xffffffffu, s_lo[mt], 2);
        s_hi[mt] += __shfl_xor_sync(0xffffffffu, s_hi[mt], 1);
        s_hi[mt] += __shfl_xor_sync(0xffffffffu, s_hi[mt], 2);
    }
    if ((lane & 3) == 0) {
#pragma unroll
        for (int mt = 0; mt < 2; mt++) {
            int rl = wm * 32 + mt * 16 + (lane >> 2);
            rowred[wn * 64 + rl]     = s_lo[mt];
            rowred[wn * 64 + rl + 8] = s_hi[mt];
        }
    }
    __syncthreads();
#pragma unroll
    for (int mt = 0; mt < 2; mt++) {
        int rl = wm * 32 + mt * 16 + (lane >> 2);
        int rh = rl + 8;
        float ssl = rowred[rl] + rowred[64 + rl] + rowred[128 + rl] + rowred[192 + rl];
        float ssh = rowred[rh] + rowred[64 + rh] + rowred[128 + rh] + rowred[192 + rh];
        float scl = 1.0f / fmaxf(sqrtf(ssl), 1e-12f);
        float sch = 1.0f / fmaxf(sqrtf(ssh), 1e-12f);
        long grl = row0 + rl, grh = row0 + rh;
#pragma unroll
        for (int nt = 0; nt < 8; nt++) {
            int col = wn * 64 + nt * 8 + (lane & 3) * 2;
            if (grl < n) {
                float2 o = make_float2(C[mt][nt][0] * scl, C[mt][nt][1] * scl);
                float* op = Out + grl * 256 + col;
                if (accum) { float2 u = *(const float2*)op; o.x += u.x; o.y += u.y; }
                *(float2*)op = o;
            }
            if (grh < n) {
                float2 o = make_float2(C[mt][nt][2] * sch, C[mt][nt][3] * sch);
                float* op = Out + grh * 256 + col;
                if (accum) { float2 u = *(const float2*)op; o.x += u.x; o.y += u.y; }
                *(float2*)op = o;
            }
        }
    }
}

// ---- final head: relu(x_reaction) @ W_out[256x128] + b_out -------------------------
__global__ __launch_bounds__(256, 2) void final_gemm(
    const float* __restrict__ A, const float* __restrict__ W,
    const float* __restrict__ bias, float* __restrict__ C, int n) {
    __shared__ float As[16][64];
    __shared__ float Bs[16][128];
    const int tid = threadIdx.x;
    const long row0 = (long)blockIdx.x * 64;
    const int m = tid & 63, kq = tid >> 6;
    const int jb = tid & 31, kb2 = tid >> 5;
    const int tcol = tid & 31, tr = tid >> 5;

    unsigned long long acc[8][2];
#pragma unroll
    for (int i = 0; i < 8; i++) { acc[i][0] = 0ULL; acc[i][1] = 0ULL; }

    const long arow = row0 + m;
    const bool aval = arow < n;

#pragma unroll 1
    for (int k0 = 0; k0 < 256; k0 += 16) {
        float4 av = make_float4(0.f, 0.f, 0.f, 0.f);
        if (aval) av = *(const float4*)&A[arow * DIM + k0 + kq * 4];
        av.x = fmaxf(av.x, 0.f); av.y = fmaxf(av.y, 0.f);
        av.z = fmaxf(av.z, 0.f); av.w = fmaxf(av.w, 0.f);
        float4 bv0 = *(const float4*)&W[(long)(k0 + kb2) * 128 + jb * 4];
        float4 bv1 = *(const float4*)&W[(long)(k0 + kb2 + 8) * 128 + jb * 4];
        __syncthreads();
        As[kq * 4 + 0][m] = av.x;
        As[kq * 4 + 1][m] = av.y;
        As[kq * 4 + 2][m] = av.z;
        As[kq * 4 + 3][m] = av.w;
        *(float4*)&Bs[kb2][jb * 4] = bv0;
        *(float4*)&Bs[kb2 + 8][jb * 4] = bv1;
        __syncthreads();
#pragma unroll
        for (int k = 0; k < 16; k++) {
            ulonglong2 b01 = *(const ulonglong2*)&Bs[k][tcol * 4];
            float4 a0 = *(const float4*)&As[k][tr * 8];
            float4 a1 = *(const float4*)&As[k][tr * 8 + 4];
            float aa[8] = {a0.x, a0.y, a0.z, a0.w, a1.x, a1.y, a1.z, a1.w};
#pragma unroll
            for (int i = 0; i < 8; i++) {
                unsigned long long a2v;
                PACK2(a2v, aa[i], aa[i]);
                FMA2(acc[i][0], a2v, b01.x);
                FMA2(acc[i][1], a2v, b01.y);
            }
        }
    }

    float4 bb = *(const float4*)&bias[tcol * 4];
    float bsv[4] = {bb.x, bb.y, bb.z, bb.w};
#pragma unroll
    for (int i = 0; i < 8; i++) {
        float v[4];
        UNPACK2(v[0], v[1], acc[i][0]);
        UNPACK2(v[2], v[3], acc[i][1]);
        long r = row0 + (long)tr * 8 + i;
        if (r < n) {
            float4 o0 = make_float4(v[0] + bsv[0], v[1] + bsv[1],
                                    v[2] + bsv[2], v[3] + bsv[3]);
            *(float4*)&C[r * 128 + tcol * 4] = o0;
        }
    }
}

// ---------------------------------------------------------------------------
extern "C" void kernel_launch(void* const* d_in, const int* in_sizes, int n_in,
                              void* d_out, int out_size) {
    const float* remb = (const float*)d_in[4];
    const float* cemb = (const float*)d_in[5];
    const float* ptab = (const float*)d_in[6];
    const float* mtab = (const float*)d_in[7];
    const float* Wl   = (const float*)d_in[8];
    const float* Wr   = (const float*)d_in[9];
    const float* bvec = (const float*)d_in[10];
    const float* Wout = (const float*)d_in[11];
    const float* bout = (const float*)d_in[12];
    const int* edge[7];
    int ecnt[7];
    for (int t = 0; t < 7; t++) {
        edge[t] = (const int*)d_in[13 + t];
        ecnt[t] = in_sizes[13 + t] / 2;
    }
    const int E = ecnt[0];                     // uniform (300000)
    const int BPT = (E * 32 + 255) / 256;      // blocks per type in fused scatter

    cudaFuncSetAttribute(mma_sage, cudaFuncAttributeMaxDynamicSharedMemorySize, SMEM_SZ);

    float *r1, *xA, *xB, *agg;
    __half* w16;
    cudaGetSymbolAddress((void**)&r1, g_r1);
    cudaGetSymbolAddress((void**)&xA, g_xA);
    cudaGetSymbolAddress((void**)&xB, g_xB);
    cudaGetSymbolAddress((void**)&agg, g_agg);
    cudaGetSymbolAddress((void**)&w16, g_W16);

    // degrees
    zero_deg_kernel<<<(DEG_TOTAL + 255) / 256, 256>>>();
    for (int t = 0; t < 7; t++)
        deg_kernel<<<(ecnt[t] + 255) / 256, 256>>>(edge[t] + ecnt[t], ecnt[t], DEGOFF[t]);

    // weight repack + rank-1 vectors
    conv_w_kernel<<<(int)((21L * 256 * 64 + 255) / 256), 256>>>(Wl, Wr);
    rank1_kernel<<<1, 256>>>(remb, Wr + 0 * 65536L, r1 + 0 * 256);
    rank1_kernel<<<1, 256>>>(remb, Wr + 1 * 65536L, r1 + 1 * 256);
    rank1_kernel<<<1, 256>>>(cemb, Wl + 2 * 65536L, r1 + 2 * 256);
    rank1_kernel<<<1, 256>>>(remb, Wr + 2 * 65536L, r1 + 3 * 256);
    rank1_kernel<<<1, 256>>>(cemb, Wr + 3 * 65536L, r1 + 4 * 256);
    rank1_kernel<<<1, 256>>>(cemb, Wr + 4 * 65536L, r1 + 5 * 256);
    rank1_kernel<<<1, 256>>>(remb, Wl + 5 * 65536L, r1 + 6 * 256);
    rank1_kernel<<<1, 256>>>(remb, Wl + 6 * 65536L, r1 + 7 * 256);
    t2_combine_kernel<<<1, 256>>>(r1 + 2 * 256, r1 + 3 * 256, bvec + 2 * 256);

    // ---------------- layer 0 ----------------
    // zero agg regions for types 0,1 ([0,200k)) and 3,4 ([300k,400k))
    zero_range_kernel<<<(int)((200000L * 64 + 255) / 256), 256>>>(0, 200000);
    zero_range_kernel<<<(int)((100000L * 64 + 255) / 256), 256>>>(300000, 100000);
    {   // fused scatter: types 0,1,3,4 (sources ptab/mtab, no relu)
        ScatP p{};
        const int ts[4] = {0, 1, 3, 4};
        const float* xs[4] = {ptab, mtab, ptab, mtab};
        for (int i = 0; i < 4; i++) {
            int t = ts[i];
            p.srcIdx[i] = edge[t];
            p.dstIdx[i] = edge[t] + ecnt[t];
            p.X[i] = xs[i];
            p.agg[i] = agg + DEGOFF[t] * DIM;
        }
        p.e = E; p.nt = 4; p.relu = 0;
        scatter_fused<<<BPT * 4, 256>>>(p);
    }
    for (int t = 0; t < 2; t++)       // dst reaction: agg-only GEMM + const
        mma_sage<<<(NNODE[0] + 63) / 64, 256, SMEM_SZ>>>(
            agg + DEGOFF[t] * DIM, nullptr, w16 + (long)t * 131072,
            bvec + (long)t * 256, r1 + t * 256, nullptr,
            xB + XOFF[0] * DIM, DEGOFF[t], NNODE[0], t == 0 ? 0 : 1, 4, 0, 0);
    t2_apply_kernel<<<(NNODE[0] * 64 + 255) / 256, 256>>>(xB + XOFF[0] * DIM, DEGOFF[2], NNODE[0]);
    for (int t = 3; t < 5; t++)       // dst complex: agg-only GEMM + const
        mma_sage<<<(NNODE[1] + 63) / 64, 256, SMEM_SZ>>>(
            agg + DEGOFF[t] * DIM, nullptr, w16 + (long)t * 131072,
            bvec + (long)t * 256, r1 + (t + 1) * 256, nullptr,
            xB + XOFF[1] * DIM, DEGOFF[t], NNODE[1], t == 3 ? 0 : 1, 4, 0, 0);
    // t5: gate*vl + ptab@Wr (x-phase only), dst protein
    mma_sage<<<(NNODE[2] + 63) / 64, 256, SMEM_SZ>>>(
        nullptr, ptab, w16 + 5L * 131072,
        bvec + 5L * 256, nullptr, r1 + 6 * 256,
        xB + XOFF[2] * DIM, DEGOFF[5], NNODE[2], 0, 0, 4, 0);
    // t6: gate*vl + mtab@Wr, dst molecule
    mma_sage<<<(NNODE[3] + 63) / 64, 256, SMEM_SZ>>>(
        nullptr, mtab, w16 + 6L * 131072,
        bvec + 6L * 256, nullptr, r1 + 7 * 256,
        xB + XOFF[3] * DIM, DEGOFF[6], NNODE[3], 0, 0, 4, 0);

    // ---------------- layer 1 (reads xB -> writes xA) ----------------
    zero_range_kernel<<<(int)((750000L * 64 + 255) / 256), 256>>>(0, 750000);
    {   // fused scatter: all 7 types from xB, relu
        ScatP p{};
        for (int t = 0; t < 7; t++) {
            p.srcIdx[t] = edge[t];
            p.dstIdx[t] = edge[t] + ecnt[t];
            p.X[t] = xB + XOFF[ET_S[t]] * DIM;
            p.agg[t] = agg + DEGOFF[t] * DIM;
        }
        p.e = E; p.nt = 7; p.relu = 1;
        scatter_fused<<<BPT * 7, 256>>>(p);
    }
    {
        const int  DN[7]  = {0, 0, 0, 1, 1, 2, 3};
        bool first[4] = {true, true, true, true};
        for (int t = 0; t < 7; t++) {
            int d = DN[t];
            mma_sage<<<(NNODE[d] + 63) / 64, 256, SMEM_SZ>>>(
                agg + DEGOFF[t] * DIM, xB + XOFF[d] * DIM,
                w16 + (long)(7 + t) * 131072,
                bvec + (long)(7 + t) * 256, nullptr, nullptr,
                xA + XOFF[d] * DIM, DEGOFF[t], NNODE[d], first[d] ? 0 : 1, 4, 4, 1);
            first[d] = false;
        }
    }

    // ---------------- layer 2 (reads xA -> writes xB, dst reaction only) -------
    zero_range_kernel<<<(int)((300000L * 64 + 255) / 256), 256>>>(0, 300000);
    {   // fused scatter: types 0,1,2 from xA, relu
        ScatP p{};
        for (int t = 0; t < 3; t++) {
            p.srcIdx[t] = edge[t];
            p.dstIdx[t] = edge[t] + ecnt[t];
            p.X[t] = xA + XOFF[ET_S[t]] * DIM;
            p.agg[t] = agg + DEGOFF[t] * DIM;
        }
        p.e = E; p.nt = 3; p.relu = 1;
        scatter_fused<<<BPT * 3, 256>>>(p);
    }
    for (int t = 0; t < 3; t++)
        mma_sage<<<(NNODE[0] + 63) / 64, 256, SMEM_SZ>>>(
            agg + DEGOFF[t] * DIM, xA + XOFF[0] * DIM,
            w16 + (long)(14 + t) * 131072,
            bvec + (long)(14 + t) * 256, nullptr, nullptr,
            xB + XOFF[0] * DIM, DEGOFF[t], NNODE[0], t == 0 ? 0 : 1, 4, 4, 1);

    // head: relu(x_reaction, in xB) @ W_out + b_out
    final_gemm<<<(NNODE[0] + 63) / 64, 256>>>(xB + XOFF[0] * DIM, Wout, bout,
                                              (float*)d_out, NNODE[0]);
}